// round 5
// baseline (speedup 1.0000x reference)
#include <cuda_runtime.h>
#include <cuda_bf16.h>
#include <cstdint>

// ===========================================================================
// DensityMatrixMLP, fused bf16 split-precision mma.sync (HMMA), round 5.
//  - 2 CTAs/SM: smem 108.5KB, launch_bounds(256,2), k-chunks of 64
//  - weights pre-converted to swizzled bf16 hi/lo device globals (prep kernel),
//    main kernel cp.asyncs them (no per-CTA convert)
//  - stage 3 exploits rho symmetry (compute j<=i, mirror)
// ===========================================================================

#define THREADS 256
#define TRIL    136
#define VS_STRIDE 137

// ---- smem layout (bytes) ----
#define OFF_B1   0              // 128 f32
#define OFF_B2   512            // 136 f32
#define OFF_TR   1088           // 128 f32
#define OFF_A    2048
// GEMM1 phase (k-chunk 64):
#define XS_HI    (OFF_A)                 // 128r x 128B
#define XS_LO    (OFF_A + 16384)
#define W1S_HI   (OFF_A + 32768)         // 64k x 256B
#define W1S_LO   (OFF_A + 49152)
// after GEMM1:
#define HS_HI    (OFF_A)                 // 128r x 256B (full k=128)
#define HS_LO    (OFF_A + 32768)
#define OFF_W2S  (OFF_A + 65536)         // 67584
#define W2S_HI   (OFF_W2S)               // 64k x 320B
#define W2S_LO   (OFF_W2S + 20480)
// stage-3 overlay (after GEMM2): Vs 128x137 f32 = 70144 B at OFF_A
#define OFF_VS   (OFF_A)
#define SMEM_BYTES (OFF_W2S + 40960)     // 108544

// ---- pre-converted weight buffers (device globals; swizzled layouts) ----
__device__ __align__(16) unsigned char g_w1hi[256 * 256];   // [256k][256B]
__device__ __align__(16) unsigned char g_w1lo[256 * 256];
__device__ __align__(16) unsigned char g_w2hi[128 * 320];   // [128k][320B], n pad->144
__device__ __align__(16) unsigned char g_w2lo[128 * 320];

static __device__ __forceinline__ uint32_t smem_u32(const void* p) {
    uint32_t a;
    asm("{ .reg .u64 t; cvta.to.shared.u64 t, %1; cvt.u32.u64 %0, t; }"
        : "=r"(a) : "l"(p));
    return a;
}

// swizzles: XOR 16B-chunk index with row&7
static __device__ __forceinline__ uint32_t swz128(int row, int bc) {
    return (uint32_t)(row * 128 + ((((bc >> 4) ^ (row & 7)) << 4) | (bc & 15)));
}
static __device__ __forceinline__ uint32_t swz256(int row, int bc) {
    return (uint32_t)(row * 256 + ((((bc >> 4) ^ (row & 7)) << 4) | (bc & 15)));
}
static __device__ __forceinline__ uint32_t swz320(int row, int bc) {
    int c = bc >> 4;
    if (c < 16) c ^= (row & 7);
    return (uint32_t)(row * 320 + (c << 4) + (bc & 15));
}
static __device__ __forceinline__ uint32_t lm128(uint32_t base, int r0, int bc0, int lane) {
    int row = r0 + (lane & 15), bc = bc0 + ((lane >> 4) << 4);
    return base + swz128(row, bc);
}
static __device__ __forceinline__ uint32_t lm256(uint32_t base, int r0, int bc0, int lane) {
    int row = r0 + (lane & 15), bc = bc0 + ((lane >> 4) << 4);
    return base + swz256(row, bc);
}
static __device__ __forceinline__ uint32_t lm320(uint32_t base, int r0, int bc0, int lane) {
    int row = r0 + (lane & 15), bc = bc0 + ((lane >> 4) << 4);
    return base + swz320(row, bc);
}

static __device__ __forceinline__ void ldsm_x4(uint32_t a, uint32_t r[4]) {
    asm volatile("ldmatrix.sync.aligned.m8n8.x4.shared.b16 {%0,%1,%2,%3}, [%4];"
                 : "=r"(r[0]), "=r"(r[1]), "=r"(r[2]), "=r"(r[3]) : "r"(a));
}
static __device__ __forceinline__ void ldsm_x4t(uint32_t a, uint32_t r[4]) {
    asm volatile("ldmatrix.sync.aligned.m8n8.x4.trans.shared.b16 {%0,%1,%2,%3}, [%4];"
                 : "=r"(r[0]), "=r"(r[1]), "=r"(r[2]), "=r"(r[3]) : "r"(a));
}
static __device__ __forceinline__ void ldsm_x2t(uint32_t a, uint32_t r[2]) {
    asm volatile("ldmatrix.sync.aligned.m8n8.x2.trans.shared.b16 {%0,%1}, [%2];"
                 : "=r"(r[0]), "=r"(r[1]) : "r"(a));
}
static __device__ __forceinline__ void mma_bf16(float d[4], const uint32_t a[4],
                                                const uint32_t* b) {
    asm volatile(
        "mma.sync.aligned.m16n8k16.row.col.f32.bf16.bf16.f32 "
        "{%0,%1,%2,%3}, {%4,%5,%6,%7}, {%8,%9}, {%0,%1,%2,%3};"
        : "+f"(d[0]), "+f"(d[1]), "+f"(d[2]), "+f"(d[3])
        : "r"(a[0]), "r"(a[1]), "r"(a[2]), "r"(a[3]), "r"(b[0]), "r"(b[1]));
}

#define CP16(dst, src) \
    asm volatile("cp.async.cg.shared.global [%0], [%1], 16;" :: "r"(dst), "l"(src))
#define CP_COMMIT() asm volatile("cp.async.commit_group;" ::: "memory")
#define CP_WAIT0()  asm volatile("cp.async.wait_group 0;" ::: "memory")

static __device__ __forceinline__ uint32_t bf2u(__nv_bfloat162 v) {
    return *reinterpret_cast<uint32_t*>(&v);
}
static __device__ __forceinline__ void split8(const float* v, uint4& h, uint4& l) {
    uint32_t hp[4], lp[4];
#pragma unroll
    for (int q = 0; q < 4; q++) {
        float a = v[2*q], b = v[2*q+1];
        __nv_bfloat162 hh = __floats2bfloat162_rn(a, b);
        float ra = a - __bfloat162float(__low2bfloat16(hh));
        float rb = b - __bfloat162float(__high2bfloat16(hh));
        __nv_bfloat162 ll = __floats2bfloat162_rn(ra, rb);
        hp[q] = bf2u(hh); lp[q] = bf2u(ll);
    }
    h = make_uint4(hp[0], hp[1], hp[2], hp[3]);
    l = make_uint4(lp[0], lp[1], lp[2], lp[3]);
}

// ---- prep kernel: W1/W2 -> swizzled bf16 hi/lo globals ----
__global__ void prep_weights(const float* __restrict__ W1,
                             const float* __restrict__ W2) {
    int t = blockIdx.x * blockDim.x + threadIdx.x;
    if (t < 32768) {                       // W1: [256k][128n]
        int k = t >> 7, n = t & 127;
        float v = W1[t];
        __nv_bfloat16 h = __float2bfloat16_rn(v);
        __nv_bfloat16 l = __float2bfloat16_rn(v - __bfloat162float(h));
        uint32_t off = (uint32_t)(k * 256 + ((((n >> 3) ^ (k & 7)) << 4) | ((n & 7) * 2)));
        *reinterpret_cast<__nv_bfloat16*>(g_w1hi + off) = h;
        *reinterpret_cast<__nv_bfloat16*>(g_w1lo + off) = l;
    } else if (t < 32768 + 128 * 144) {    // W2: [128k][144n], n>=136 pad zero
        int u = t - 32768;
        int k = u / 144, n = u - k * 144;
        float v = (n < TRIL) ? W2[k * TRIL + n] : 0.f;
        __nv_bfloat16 h = __float2bfloat16_rn(v);
        __nv_bfloat16 l = __float2bfloat16_rn(v - __bfloat162float(h));
        int c = n >> 3; if (c < 16) c ^= (k & 7);
        uint32_t off = (uint32_t)(k * 320 + (c << 4) + ((n & 7) * 2));
        *reinterpret_cast<__nv_bfloat16*>(g_w2hi + off) = h;
        *reinterpret_cast<__nv_bfloat16*>(g_w2lo + off) = l;
    }
}

// ---- stage 3: symmetric rho row (compute j<=I, mirror) ----
template <int I>
static __device__ __forceinline__ void rho_row_sym(const float* __restrict__ vrow,
                                                   float invtr,
                                                   float* __restrict__ orow) {
    constexpr int TI = I * (I + 1) / 2;
    float Li[I + 1];
#pragma unroll
    for (int k = 0; k <= I; k++) Li[k] = vrow[TI + k];
#pragma unroll
    for (int j = 0; j <= I; j++) {
        const int tj = j * (j + 1) / 2;
        float dot = 0.f;
#pragma unroll
        for (int k = 0; k <= j; k++) dot = fmaf(Li[k], vrow[tj + k], dot);
        float val = dot * invtr;
        orow[I * 16 + j] = val;
        if (j < I) orow[j * 16 + I] = val;
    }
}

__global__ void __launch_bounds__(THREADS, 2)
density_mlp_hmma(const float* __restrict__ x,
                 const float* __restrict__ b1,
                 const float* __restrict__ b2,
                 float* __restrict__ out) {
    extern __shared__ char smem[];
    const uint32_t sb = smem_u32(smem);
    const int tid  = threadIdx.x;
    const int wid  = tid >> 5;
    const int lane = tid & 31;
    const int brow = blockIdx.x * 128;

    float* bias1 = reinterpret_cast<float*>(smem + OFF_B1);
    float* bias2 = reinterpret_cast<float*>(smem + OFF_B2);
    float* trc   = reinterpret_cast<float*>(smem + OFF_TR);

    if (tid < 128) { bias1[tid] = b1[tid]; trc[tid] = 0.f; }
    if (tid < TRIL) bias2[tid] = b2[tid];

    const int m0  = (wid >> 1) * 32;
    const int n0g = (wid & 1) * 64;

    // ======================= GEMM1: 4 K-chunks of 64 ========================
    float acc[2][8][4];
#pragma unroll
    for (int mt = 0; mt < 2; mt++)
#pragma unroll
    for (int nt = 0; nt < 8; nt++)
#pragma unroll
    for (int q = 0; q < 4; q++) acc[mt][nt][q] = 0.f;

    for (int c = 0; c < 4; c++) {
        if (c) __syncthreads();            // prev chunk mma done
        // W1 chunk via cp.async (pre-swizzled slabs, contiguous 16KB/half)
        {
            const unsigned char* sh = g_w1hi + c * 16384;
            const unsigned char* sl = g_w1lo + c * 16384;
#pragma unroll
            for (int i = 0; i < 4; i++) {
                int u = tid + i * THREADS;
                CP16(sb + W1S_HI + u * 16, sh + u * 16);
                CP16(sb + W1S_LO + u * 16, sl + u * 16);
            }
            CP_COMMIT();
        }
        // X chunk [128r x 64k]: load fp32, split, swizzled store
#pragma unroll
        for (int i = 0; i < 4; i++) {
            int u = tid + i * THREADS;     // 0..1023
            int row = u >> 3, j = u & 7;
            const float* s = x + (size_t)(brow + row) * 256 + c * 64 + j * 8;
            float4 p = *reinterpret_cast<const float4*>(s);
            float4 q4 = *reinterpret_cast<const float4*>(s + 4);
            float v[8] = {p.x, p.y, p.z, p.w, q4.x, q4.y, q4.z, q4.w};
            uint4 h, l; split8(v, h, l);
            uint32_t off = swz128(row, j * 16);
            *reinterpret_cast<uint4*>(smem + XS_HI + off) = h;
            *reinterpret_cast<uint4*>(smem + XS_LO + off) = l;
        }
        CP_WAIT0();
        __syncthreads();

#pragma unroll
        for (int kt = 0; kt < 4; kt++) {
            uint32_t ah[2][4], al[2][4];
            ldsm_x4(lm128(sb + XS_HI, m0,      kt * 32, lane), ah[0]);
            ldsm_x4(lm128(sb + XS_HI, m0 + 16, kt * 32, lane), ah[1]);
            ldsm_x4(lm128(sb + XS_LO, m0,      kt * 32, lane), al[0]);
            ldsm_x4(lm128(sb + XS_LO, m0 + 16, kt * 32, lane), al[1]);
#pragma unroll
            for (int p = 0; p < 4; p++) {
                uint32_t th[4], tl[4];
                ldsm_x4t(lm256(sb + W1S_HI, kt * 16, (n0g + p * 16) * 2, lane), th);
                ldsm_x4t(lm256(sb + W1S_LO, kt * 16, (n0g + p * 16) * 2, lane), tl);
#pragma unroll
                for (int mt = 0; mt < 2; mt++) {
                    mma_bf16(acc[mt][2*p],   ah[mt], th);
                    mma_bf16(acc[mt][2*p],   ah[mt], tl);
                    mma_bf16(acc[mt][2*p],   al[mt], th);
                    mma_bf16(acc[mt][2*p+1], ah[mt], th + 2);
                    mma_bf16(acc[mt][2*p+1], ah[mt], tl + 2);
                    mma_bf16(acc[mt][2*p+1], al[mt], th + 2);
                }
            }
        }
    }
    __syncthreads();

    // ============== epilogue 1: H = relu(C1+b1) -> HS hi/lo =================
#pragma unroll
    for (int mt = 0; mt < 2; mt++)
#pragma unroll
    for (int nt = 0; nt < 8; nt++) {
        int col = n0g + nt * 8 + ((lane & 3) << 1);
        float ba = bias1[col], bb = bias1[col + 1];
        int r = m0 + mt * 16 + (lane >> 2);
#pragma unroll
        for (int half = 0; half < 2; half++) {
            float v0 = fmaxf(acc[mt][nt][2*half]     + ba, 0.f);
            float v1 = fmaxf(acc[mt][nt][2*half + 1] + bb, 0.f);
            __nv_bfloat162 hh = __floats2bfloat162_rn(v0, v1);
            float r0 = v0 - __bfloat162float(__low2bfloat16(hh));
            float r1 = v1 - __bfloat162float(__high2bfloat16(hh));
            __nv_bfloat162 ll = __floats2bfloat162_rn(r0, r1);
            uint32_t off = swz256(r + half * 8, col * 2);
            *reinterpret_cast<uint32_t*>(smem + HS_HI + off) = bf2u(hh);
            *reinterpret_cast<uint32_t*>(smem + HS_LO + off) = bf2u(ll);
        }
    }

    // ======================= GEMM2: 2 K-chunks of 64 ========================
    const int n0g2 = (wid & 1) * 72;
    float acc2[2][9][4];
#pragma unroll
    for (int mt = 0; mt < 2; mt++)
#pragma unroll
    for (int nt = 0; nt < 9; nt++)
#pragma unroll
    for (int q = 0; q < 4; q++) acc2[mt][nt][q] = 0.f;

    for (int c2 = 0; c2 < 2; c2++) {
        // W2 chunk via cp.async (20KB/half, contiguous)
        {
            const unsigned char* sh = g_w2hi + c2 * 20480;
            const unsigned char* sl = g_w2lo + c2 * 20480;
#pragma unroll
            for (int i = 0; i < 5; i++) {
                int u = tid + i * THREADS;
                CP16(sb + W2S_HI + u * 16, sh + u * 16);
                CP16(sb + W2S_LO + u * 16, sl + u * 16);
            }
            CP_COMMIT();
        }
        CP_WAIT0();
        __syncthreads();                    // also orders epilogue-1 H stores (c2=0)

#pragma unroll
        for (int kt = 0; kt < 4; kt++) {
            uint32_t ah[2][4], al[2][4];
            int bc0 = c2 * 128 + kt * 32;
            ldsm_x4(lm256(sb + HS_HI, m0,      bc0, lane), ah[0]);
            ldsm_x4(lm256(sb + HS_HI, m0 + 16, bc0, lane), ah[1]);
            ldsm_x4(lm256(sb + HS_LO, m0,      bc0, lane), al[0]);
            ldsm_x4(lm256(sb + HS_LO, m0 + 16, bc0, lane), al[1]);
#pragma unroll
            for (int p = 0; p < 4; p++) {
                uint32_t th[4], tl[4];
                ldsm_x4t(lm320(sb + W2S_HI, kt * 16, (n0g2 + p * 16) * 2, lane), th);
                ldsm_x4t(lm320(sb + W2S_LO, kt * 16, (n0g2 + p * 16) * 2, lane), tl);
#pragma unroll
                for (int mt = 0; mt < 2; mt++) {
                    mma_bf16(acc2[mt][2*p],   ah[mt], th);
                    mma_bf16(acc2[mt][2*p],   ah[mt], tl);
                    mma_bf16(acc2[mt][2*p],   al[mt], th);
                    mma_bf16(acc2[mt][2*p+1], ah[mt], th + 2);
                    mma_bf16(acc2[mt][2*p+1], ah[mt], tl + 2);
                    mma_bf16(acc2[mt][2*p+1], al[mt], th + 2);
                }
            }
            {
                uint32_t bh8[2], bl8[2];
                ldsm_x2t(lm320(sb + W2S_HI, kt * 16, (n0g2 + 64) * 2, lane), bh8);
                ldsm_x2t(lm320(sb + W2S_LO, kt * 16, (n0g2 + 64) * 2, lane), bl8);
#pragma unroll
                for (int mt = 0; mt < 2; mt++) {
                    mma_bf16(acc2[mt][8], ah[mt], bh8);
                    mma_bf16(acc2[mt][8], ah[mt], bl8);
                    mma_bf16(acc2[mt][8], al[mt], bh8);
                }
            }
        }
        __syncthreads();                    // before W2 buffer reuse / Vs overlay
    }

    // ============ epilogue 2: V -> Vs, trace via smem atomics ===============
    {
        float* Vs = reinterpret_cast<float*>(smem + OFF_VS);
        float part[2][2] = {{0.f, 0.f}, {0.f, 0.f}};
#pragma unroll
        for (int mt = 0; mt < 2; mt++)
#pragma unroll
        for (int nt = 0; nt < 9; nt++) {
            int col = n0g2 + nt * 8 + ((lane & 3) << 1);
            if (col < TRIL) {
                float ba = bias2[col];
                float bb = (col + 1 < TRIL) ? bias2[col + 1] : 0.f;
                int r = m0 + mt * 16 + (lane >> 2);
#pragma unroll
                for (int half = 0; half < 2; half++) {
                    float v0 = acc2[mt][nt][2*half] + ba;
                    Vs[(r + half*8) * VS_STRIDE + col] = v0;
                    part[mt][half] = fmaf(v0, v0, part[mt][half]);
                    if (col + 1 < TRIL) {
                        float v1 = acc2[mt][nt][2*half + 1] + bb;
                        Vs[(r + half*8) * VS_STRIDE + col + 1] = v1;
                        part[mt][half] = fmaf(v1, v1, part[mt][half]);
                    }
                }
            }
        }
#pragma unroll
        for (int mt = 0; mt < 2; mt++)
#pragma unroll
        for (int half = 0; half < 2; half++)
            atomicAdd(&trc[m0 + mt * 16 + (lane >> 2) + half * 8], part[mt][half]);
    }
    __syncthreads();

    // ============== stage 3: rho = L L^T / trace (symmetric) ================
    {
        const float* Vs = reinterpret_cast<const float*>(smem + OFF_VS);
        const int row = tid & 127;
        const int ib  = tid >> 7;
        const float* vrow = &Vs[row * VS_STRIDE];
        const float invtr = 1.0f / trc[row];
        float* orow = &out[(size_t)(brow + row) * 256];
        if (ib == 0) {
            rho_row_sym<0>(vrow, invtr, orow);  rho_row_sym<2>(vrow, invtr, orow);
            rho_row_sym<4>(vrow, invtr, orow);  rho_row_sym<6>(vrow, invtr, orow);
            rho_row_sym<8>(vrow, invtr, orow);  rho_row_sym<10>(vrow, invtr, orow);
            rho_row_sym<12>(vrow, invtr, orow); rho_row_sym<14>(vrow, invtr, orow);
        } else {
            rho_row_sym<1>(vrow, invtr, orow);  rho_row_sym<3>(vrow, invtr, orow);
            rho_row_sym<5>(vrow, invtr, orow);  rho_row_sym<7>(vrow, invtr, orow);
            rho_row_sym<9>(vrow, invtr, orow);  rho_row_sym<11>(vrow, invtr, orow);
            rho_row_sym<13>(vrow, invtr, orow); rho_row_sym<15>(vrow, invtr, orow);
        }
    }
}

extern "C" void kernel_launch(void* const* d_in, const int* in_sizes, int n_in,
                              void* d_out, int out_size) {
    const float* x  = (const float*)d_in[0];
    const float* W1 = (const float*)d_in[1];
    const float* b1 = (const float*)d_in[2];
    const float* W2 = (const float*)d_in[3];
    const float* b2 = (const float*)d_in[4];
    float* out = (float*)d_out;

    const int batch  = in_sizes[0] / 256;   // 131072
    const int blocks = batch / 128;         // 1024

    prep_weights<<<200, 256>>>(W1, W2);

    cudaFuncSetAttribute(density_mlp_hmma,
                         cudaFuncAttributeMaxDynamicSharedMemorySize, SMEM_BYTES);
    density_mlp_hmma<<<blocks, THREADS, SMEM_BYTES>>>(x, b1, b2, out);
}

// round 6
// speedup vs baseline: 1.0695x; 1.0695x over previous
#include <cuda_runtime.h>
#include <cuda_bf16.h>
#include <cstdint>

// ===========================================================================
// DensityMatrixMLP, fused bf16 split-precision mma.sync (HMMA), round 6.
// Round-4 skeleton (1 CTA/SM, 256 thr, 32m x 64n warp tiles, no reg cap) +
//  - weights pre-converted to swizzled bf16 hi/lo device globals (prep kernel)
//  - cp.async double-buffered weight prefetch overlapped with mainloops
//  - symmetric stage-3 (compute j<=i, mirror)
// ===========================================================================

#define THREADS 256
#define TRIL    136
#define VS_STRIDE 137

// ---- smem layout (bytes) ----
#define OFF_B1   0              // 128 f32
#define OFF_B2   512            // 136 f32
#define OFF_TR   1088           // 128 f32
#define OFF_A    2048           // X / H region, 64 KB
#define XHI      (OFF_A)                 // 128r x 256B (128 k bf16)
#define XLO      (OFF_A + 32768)
#define HHI      (OFF_A)                 // overlay after GEMM1
#define HLO      (OFF_A + 32768)
#define WBUF0    (OFF_A + 65536)         // weight buffer 0, 64 KB
#define WBUF1    (WBUF0 + 65536)         // weight buffer 1, 64 KB
// W1 chunk in WBUFx: HI at +0 (32KB), LO at +32768
// W2 chunk in WBUFx: HI at +0 (20KB), LO at +20480
#define W2LO_OFF 20480
#define OFF_VS   (WBUF0)                 // Vs overlay after GEMM2 (70144 B)
#define SMEM_BYTES (WBUF1 + 65536)       // 198656

// ---- pre-converted weight buffers (swizzled layouts) ----
__device__ __align__(16) unsigned char g_w1hi[256 * 256];   // [256k][256B]
__device__ __align__(16) unsigned char g_w1lo[256 * 256];
__device__ __align__(16) unsigned char g_w2hi[128 * 320];   // [128k][320B], n->144 pad
__device__ __align__(16) unsigned char g_w2lo[128 * 320];

static __device__ __forceinline__ uint32_t smem_u32(const void* p) {
    uint32_t a;
    asm("{ .reg .u64 t; cvta.to.shared.u64 t, %1; cvt.u32.u64 %0, t; }"
        : "=r"(a) : "l"(p));
    return a;
}

static __device__ __forceinline__ uint32_t swz256(int row, int bc) {
    return (uint32_t)(row * 256 + ((((bc >> 4) ^ (row & 7)) << 4) | (bc & 15)));
}
static __device__ __forceinline__ uint32_t swz320(int row, int bc) {
    int c = bc >> 4;
    if (c < 16) c ^= (row & 7);
    return (uint32_t)(row * 320 + (c << 4) + (bc & 15));
}
static __device__ __forceinline__ uint32_t lm256(uint32_t base, int r0, int bc0, int lane) {
    int row = r0 + (lane & 15), bc = bc0 + ((lane >> 4) << 4);
    return base + swz256(row, bc);
}
static __device__ __forceinline__ uint32_t lm320(uint32_t base, int r0, int bc0, int lane) {
    int row = r0 + (lane & 15), bc = bc0 + ((lane >> 4) << 4);
    return base + swz320(row, bc);
}

static __device__ __forceinline__ void ldsm_x4(uint32_t a, uint32_t r[4]) {
    asm volatile("ldmatrix.sync.aligned.m8n8.x4.shared.b16 {%0,%1,%2,%3}, [%4];"
                 : "=r"(r[0]), "=r"(r[1]), "=r"(r[2]), "=r"(r[3]) : "r"(a));
}
static __device__ __forceinline__ void ldsm_x4t(uint32_t a, uint32_t r[4]) {
    asm volatile("ldmatrix.sync.aligned.m8n8.x4.trans.shared.b16 {%0,%1,%2,%3}, [%4];"
                 : "=r"(r[0]), "=r"(r[1]), "=r"(r[2]), "=r"(r[3]) : "r"(a));
}
static __device__ __forceinline__ void ldsm_x2t(uint32_t a, uint32_t r[2]) {
    asm volatile("ldmatrix.sync.aligned.m8n8.x2.trans.shared.b16 {%0,%1}, [%2];"
                 : "=r"(r[0]), "=r"(r[1]) : "r"(a));
}
static __device__ __forceinline__ void mma_bf16(float d[4], const uint32_t a[4],
                                                const uint32_t* b) {
    asm volatile(
        "mma.sync.aligned.m16n8k16.row.col.f32.bf16.bf16.f32 "
        "{%0,%1,%2,%3}, {%4,%5,%6,%7}, {%8,%9}, {%0,%1,%2,%3};"
        : "+f"(d[0]), "+f"(d[1]), "+f"(d[2]), "+f"(d[3])
        : "r"(a[0]), "r"(a[1]), "r"(a[2]), "r"(a[3]), "r"(b[0]), "r"(b[1]));
}

#define CP16(dst, src) \
    asm volatile("cp.async.cg.shared.global [%0], [%1], 16;" :: "r"(dst), "l"(src))
#define CP_COMMIT() asm volatile("cp.async.commit_group;" ::: "memory")
#define CP_WAIT0()  asm volatile("cp.async.wait_group 0;" ::: "memory")
#define CP_WAIT1()  asm volatile("cp.async.wait_group 1;" ::: "memory")

static __device__ __forceinline__ uint32_t bf2u(__nv_bfloat162 v) {
    return *reinterpret_cast<uint32_t*>(&v);
}
static __device__ __forceinline__ void split8(const float* v, uint4& h, uint4& l) {
    uint32_t hp[4], lp[4];
#pragma unroll
    for (int q = 0; q < 4; q++) {
        float a = v[2*q], b = v[2*q+1];
        __nv_bfloat162 hh = __floats2bfloat162_rn(a, b);
        float ra = a - __bfloat162float(__low2bfloat16(hh));
        float rb = b - __bfloat162float(__high2bfloat16(hh));
        __nv_bfloat162 ll = __floats2bfloat162_rn(ra, rb);
        hp[q] = bf2u(hh); lp[q] = bf2u(ll);
    }
    h = make_uint4(hp[0], hp[1], hp[2], hp[3]);
    l = make_uint4(lp[0], lp[1], lp[2], lp[3]);
}

// ---- prep kernel: W1/W2 -> swizzled bf16 hi/lo globals ----
__global__ void prep_weights(const float* __restrict__ W1,
                             const float* __restrict__ W2) {
    int t = blockIdx.x * blockDim.x + threadIdx.x;
    if (t < 32768) {                       // W1: [256k][128n]
        int k = t >> 7, n = t & 127;
        float v = W1[t];
        __nv_bfloat16 h = __float2bfloat16_rn(v);
        __nv_bfloat16 l = __float2bfloat16_rn(v - __bfloat162float(h));
        uint32_t off = (uint32_t)(k * 256 + ((((n >> 3) ^ (k & 7)) << 4) | ((n & 7) * 2)));
        *reinterpret_cast<__nv_bfloat16*>(g_w1hi + off) = h;
        *reinterpret_cast<__nv_bfloat16*>(g_w1lo + off) = l;
    } else if (t < 32768 + 128 * 144) {    // W2: [128k][144n], n>=136 pad zero
        int u = t - 32768;
        int k = u / 144, n = u - k * 144;
        float v = (n < TRIL) ? W2[k * TRIL + n] : 0.f;
        __nv_bfloat16 h = __float2bfloat16_rn(v);
        __nv_bfloat16 l = __float2bfloat16_rn(v - __bfloat162float(h));
        int c = n >> 3; if (c < 16) c ^= (k & 7);
        uint32_t off = (uint32_t)(k * 320 + (c << 4) + ((n & 7) * 2));
        *reinterpret_cast<__nv_bfloat16*>(g_w2hi + off) = h;
        *reinterpret_cast<__nv_bfloat16*>(g_w2lo + off) = l;
    }
}

// ---- stage 3: symmetric rho row ----
template <int I>
static __device__ __forceinline__ void rho_row_sym(const float* __restrict__ vrow,
                                                   float invtr,
                                                   float* __restrict__ orow) {
    constexpr int TI = I * (I + 1) / 2;
    float Li[I + 1];
#pragma unroll
    for (int k = 0; k <= I; k++) Li[k] = vrow[TI + k];
#pragma unroll
    for (int j = 0; j <= I; j++) {
        const int tj = j * (j + 1) / 2;
        float dot = 0.f;
#pragma unroll
        for (int k = 0; k <= j; k++) dot = fmaf(Li[k], vrow[tj + k], dot);
        float val = dot * invtr;
        orow[I * 16 + j] = val;
        if (j < I) orow[j * 16 + I] = val;
    }
}

__global__ void __launch_bounds__(THREADS, 1)
density_mlp_hmma(const float* __restrict__ x,
                 const float* __restrict__ b1,
                 const float* __restrict__ b2,
                 float* __restrict__ out) {
    extern __shared__ char smem[];
    const uint32_t sb = smem_u32(smem);
    const int tid  = threadIdx.x;
    const int wid  = tid >> 5;
    const int lane = tid & 31;
    const int brow = blockIdx.x * 128;

    float* bias1 = reinterpret_cast<float*>(smem + OFF_B1);
    float* bias2 = reinterpret_cast<float*>(smem + OFF_B2);
    float* trc   = reinterpret_cast<float*>(smem + OFF_TR);

    if (tid < 128) { bias1[tid] = b1[tid]; trc[tid] = 0.f; }
    if (tid < TRIL) bias2[tid] = b2[tid];

    const int m0  = (wid >> 1) * 32;
    const int n0g = (wid & 1) * 64;

    // ---- prefetch helpers ----
    // W1 chunk c (64KB) -> buffer buf
    auto cp_w1 = [&](int c, uint32_t buf) {
        const unsigned char* sh = g_w1hi + c * 32768;
        const unsigned char* sl = g_w1lo + c * 32768;
#pragma unroll
        for (int i = 0; i < 8; i++) {
            int u = tid + i * THREADS;               // 0..2047
            CP16(sb + buf + u * 16, sh + u * 16);
            CP16(sb + buf + 32768 + u * 16, sl + u * 16);
        }
        CP_COMMIT();
    };
    // W2 chunk c2 (40KB) -> buffer buf
    auto cp_w2 = [&](int c2, uint32_t buf) {
        const unsigned char* sh = g_w2hi + c2 * 20480;
        const unsigned char* sl = g_w2lo + c2 * 20480;
#pragma unroll
        for (int i = 0; i < 5; i++) {
            int u = tid + i * THREADS;               // 0..1279
            CP16(sb + buf + u * 16, sh + u * 16);
            CP16(sb + buf + W2LO_OFF + u * 16, sl + u * 16);
        }
        CP_COMMIT();
    };
    // X chunk c conversion (fp32 -> bf16 hi/lo, swizzled)
    auto cvt_x = [&](int c) {
#pragma unroll
        for (int i = 0; i < 8; i++) {
            int u = tid + i * THREADS;               // 0..2047
            int row = u >> 4, j = u & 15;
            const float* s = x + (size_t)(brow + row) * 256 + c * 128 + j * 8;
            float4 p = *reinterpret_cast<const float4*>(s);
            float4 q4 = *reinterpret_cast<const float4*>(s + 4);
            float v[8] = {p.x, p.y, p.z, p.w, q4.x, q4.y, q4.z, q4.w};
            uint4 h, l; split8(v, h, l);
            uint32_t off = swz256(row, j * 16);
            *reinterpret_cast<uint4*>(smem + XHI + off) = h;
            *reinterpret_cast<uint4*>(smem + XLO + off) = l;
        }
    };

    // ======================= GEMM1: 2 K-chunks of 128 =======================
    float acc[2][8][4];
#pragma unroll
    for (int mt = 0; mt < 2; mt++)
#pragma unroll
    for (int nt = 0; nt < 8; nt++)
#pragma unroll
    for (int q = 0; q < 4; q++) acc[mt][nt][q] = 0.f;

    cp_w1(0, WBUF0);        // g0
    cp_w1(1, WBUF1);        // g1
    cvt_x(0);
    CP_WAIT1();             // g0 done (g1 may be in flight)
    __syncthreads();

    for (int c = 0; c < 2; c++) {
        const uint32_t wb = sb + (c ? WBUF1 : WBUF0);
#pragma unroll
        for (int kt = 0; kt < 8; kt++) {
            uint32_t ah[2][4], al[2][4];
            ldsm_x4(lm256(sb + XHI, m0,      kt * 32, lane), ah[0]);
            ldsm_x4(lm256(sb + XHI, m0 + 16, kt * 32, lane), ah[1]);
            ldsm_x4(lm256(sb + XLO, m0,      kt * 32, lane), al[0]);
            ldsm_x4(lm256(sb + XLO, m0 + 16, kt * 32, lane), al[1]);
#pragma unroll
            for (int p = 0; p < 4; p++) {
                uint32_t th[4], tl[4];
                ldsm_x4t(lm256(wb,         kt * 16, (n0g + p * 16) * 2, lane), th);
                ldsm_x4t(lm256(wb + 32768, kt * 16, (n0g + p * 16) * 2, lane), tl);
#pragma unroll
                for (int mt = 0; mt < 2; mt++) {
                    mma_bf16(acc[mt][2*p],   ah[mt], th);
                    mma_bf16(acc[mt][2*p],   ah[mt], tl);
                    mma_bf16(acc[mt][2*p],   al[mt], th);
                    mma_bf16(acc[mt][2*p+1], ah[mt], th + 2);
                    mma_bf16(acc[mt][2*p+1], ah[mt], tl + 2);
                    mma_bf16(acc[mt][2*p+1], al[mt], th + 2);
                }
            }
        }
        if (c == 0) {
            __syncthreads();          // all warps done with WBUF0 + X chunk 0
            cp_w2(0, WBUF0);          // g2: W2 chunk 0 into freed buffer
            cvt_x(1);                 // overwrite X region with chunk 1
            CP_WAIT1();               // g1 (W1 c1) done; g2 may be in flight
            __syncthreads();
        }
    }

    // ============== epilogue 1: H = relu(C1+b1) -> HS hi/lo =================
    // (rows are warp-private in both GEMM1 reads and these writes: no sync)
#pragma unroll
    for (int mt = 0; mt < 2; mt++)
#pragma unroll
    for (int nt = 0; nt < 8; nt++) {
        int col = n0g + nt * 8 + ((lane & 3) << 1);
        float ba = bias1[col], bb = bias1[col + 1];
        int r = m0 + mt * 16 + (lane >> 2);
#pragma unroll
        for (int half = 0; half < 2; half++) {
            float v0 = fmaxf(acc[mt][nt][2*half]     + ba, 0.f);
            float v1 = fmaxf(acc[mt][nt][2*half + 1] + bb, 0.f);
            __nv_bfloat162 hh = __floats2bfloat162_rn(v0, v1);
            float r0 = v0 - __bfloat162float(__low2bfloat16(hh));
            float r1 = v1 - __bfloat162float(__high2bfloat16(hh));
            __nv_bfloat162 ll = __floats2bfloat162_rn(r0, r1);
            uint32_t off = swz256(r + half * 8, col * 2);
            *reinterpret_cast<uint32_t*>(smem + HHI + off) = bf2u(hh);
            *reinterpret_cast<uint32_t*>(smem + HLO + off) = bf2u(ll);
        }
    }
    CP_WAIT0();                 // g2 (W2 chunk 0) landed
    __syncthreads();            // H visible to all warps; WBUF1 free
    cp_w2(1, WBUF1);            // g3: W2 chunk 1

    // ======================= GEMM2: 2 K-chunks of 64 ========================
    const int n0g2 = (wid & 1) * 72;
    float acc2[2][9][4];
#pragma unroll
    for (int mt = 0; mt < 2; mt++)
#pragma unroll
    for (int nt = 0; nt < 9; nt++)
#pragma unroll
    for (int q = 0; q < 4; q++) acc2[mt][nt][q] = 0.f;

    for (int c2 = 0; c2 < 2; c2++) {
        if (c2 == 1) { CP_WAIT0(); __syncthreads(); }   // g3 landed, visible
        const uint32_t wbh = sb + (c2 ? WBUF1 : WBUF0);
        const uint32_t wbl = wbh + W2LO_OFF;
#pragma unroll
        for (int kt = 0; kt < 4; kt++) {
            uint32_t ah[2][4], al[2][4];
            int bc0 = c2 * 128 + kt * 32;
            ldsm_x4(lm256(sb + HHI, m0,      bc0, lane), ah[0]);
            ldsm_x4(lm256(sb + HHI, m0 + 16, bc0, lane), ah[1]);
            ldsm_x4(lm256(sb + HLO, m0,      bc0, lane), al[0]);
            ldsm_x4(lm256(sb + HLO, m0 + 16, bc0, lane), al[1]);
#pragma unroll
            for (int p = 0; p < 4; p++) {
                uint32_t th[4], tl[4];
                ldsm_x4t(lm320(wbh, kt * 16, (n0g2 + p * 16) * 2, lane), th);
                ldsm_x4t(lm320(wbl, kt * 16, (n0g2 + p * 16) * 2, lane), tl);
#pragma unroll
                for (int mt = 0; mt < 2; mt++) {
                    mma_bf16(acc2[mt][2*p],   ah[mt], th);
                    mma_bf16(acc2[mt][2*p],   ah[mt], tl);
                    mma_bf16(acc2[mt][2*p],   al[mt], th);
                    mma_bf16(acc2[mt][2*p+1], ah[mt], th + 2);
                    mma_bf16(acc2[mt][2*p+1], ah[mt], tl + 2);
                    mma_bf16(acc2[mt][2*p+1], al[mt], th + 2);
                }
            }
            {
                uint32_t bh8[2], bl8[2];
                ldsm_x2t(lm320(wbh, kt * 16, (n0g2 + 64) * 2, lane), bh8);
                ldsm_x2t(lm320(wbl, kt * 16, (n0g2 + 64) * 2, lane), bl8);
#pragma unroll
                for (int mt = 0; mt < 2; mt++) {
                    mma_bf16(acc2[mt][8], ah[mt], bh8);
                    mma_bf16(acc2[mt][8], ah[mt], bl8);
                    mma_bf16(acc2[mt][8], al[mt], bh8);
                }
            }
        }
    }
    __syncthreads();            // all warps done reading W2 buffers (Vs overlay)

    // ============ epilogue 2: V -> Vs, trace via smem atomics ===============
    {
        float* Vs = reinterpret_cast<float*>(smem + OFF_VS);
        float part[2][2] = {{0.f, 0.f}, {0.f, 0.f}};
#pragma unroll
        for (int mt = 0; mt < 2; mt++)
#pragma unroll
        for (int nt = 0; nt < 9; nt++) {
            int col = n0g2 + nt * 8 + ((lane & 3) << 1);
            if (col < TRIL) {
                float ba = bias2[col];
                float bb = (col + 1 < TRIL) ? bias2[col + 1] : 0.f;
                int r = m0 + mt * 16 + (lane >> 2);
#pragma unroll
                for (int half = 0; half < 2; half++) {
                    float v0 = acc2[mt][nt][2*half] + ba;
                    Vs[(r + half*8) * VS_STRIDE + col] = v0;
                    part[mt][half] = fmaf(v0, v0, part[mt][half]);
                    if (col + 1 < TRIL) {
                        float v1 = acc2[mt][nt][2*half + 1] + bb;
                        Vs[(r + half*8) * VS_STRIDE + col + 1] = v1;
                        part[mt][half] = fmaf(v1, v1, part[mt][half]);
                    }
                }
            }
        }
#pragma unroll
        for (int mt = 0; mt < 2; mt++)
#pragma unroll
        for (int half = 0; half < 2; half++)
            atomicAdd(&trc[m0 + mt * 16 + (lane >> 2) + half * 8], part[mt][half]);
    }
    __syncthreads();

    // ============== stage 3: rho = L L^T / trace (symmetric) ================
    {
        const float* Vs = reinterpret_cast<const float*>(smem + OFF_VS);
        const int row = tid & 127;
        const int ib  = tid >> 7;
        const float* vrow = &Vs[row * VS_STRIDE];
        const float invtr = 1.0f / trc[row];
        float* orow = &out[(size_t)(brow + row) * 256];
        if (ib == 0) {
            rho_row_sym<0>(vrow, invtr, orow);  rho_row_sym<2>(vrow, invtr, orow);
            rho_row_sym<4>(vrow, invtr, orow);  rho_row_sym<6>(vrow, invtr, orow);
            rho_row_sym<8>(vrow, invtr, orow);  rho_row_sym<10>(vrow, invtr, orow);
            rho_row_sym<12>(vrow, invtr, orow); rho_row_sym<14>(vrow, invtr, orow);
        } else {
            rho_row_sym<1>(vrow, invtr, orow);  rho_row_sym<3>(vrow, invtr, orow);
            rho_row_sym<5>(vrow, invtr, orow);  rho_row_sym<7>(vrow, invtr, orow);
            rho_row_sym<9>(vrow, invtr, orow);  rho_row_sym<11>(vrow, invtr, orow);
            rho_row_sym<13>(vrow, invtr, orow); rho_row_sym<15>(vrow, invtr, orow);
        }
    }
}

extern "C" void kernel_launch(void* const* d_in, const int* in_sizes, int n_in,
                              void* d_out, int out_size) {
    const float* x  = (const float*)d_in[0];
    const float* W1 = (const float*)d_in[1];
    const float* b1 = (const float*)d_in[2];
    const float* W2 = (const float*)d_in[3];
    const float* b2 = (const float*)d_in[4];
    float* out = (float*)d_out;

    const int batch  = in_sizes[0] / 256;   // 131072
    const int blocks = batch / 128;         // 1024

    prep_weights<<<200, 256>>>(W1, W2);

    cudaFuncSetAttribute(density_mlp_hmma,
                         cudaFuncAttributeMaxDynamicSharedMemorySize, SMEM_BYTES);
    density_mlp_hmma<<<blocks, THREADS, SMEM_BYTES>>>(x, b1, b2, out);
}

// round 8
// speedup vs baseline: 1.0835x; 1.0131x over previous
#include <cuda_runtime.h>
#include <cuda_bf16.h>
#include <cstdint>

// ===========================================================================
// DensityMatrixMLP, fused bf16 split-precision mma.sync (HMMA), round 7.
// Round-4 structure exactly (known-good regalloc, 1 CTA/SM, 256 thr,
// 32m x 64n warp tiles), with register-neutral upgrades:
//  - weights pre-converted to swizzled bf16 hi/lo globals (prep kernel),
//    loaded via bare cp.async copies (no held registers, no double buffer)
//  - symmetric stage-3 (compute j<=i, mirror)
//  - shfl-reduced trace partials (4x fewer smem atomics)
// ===========================================================================

#define THREADS 256
#define TRIL    136
#define VS_STRIDE 137

// ---- smem layout (bytes) ---- (identical to round 4)
#define OFF_B1   0            // 128 f32
#define OFF_B2   512          // 136 f32
#define OFF_TR   1088         // 128 f32
#define OFF_A    2048         // 64 KB region
#define XHI      (OFF_A)              // 128r x 256B (128 k bf16)
#define XLO      (OFF_A + 32768)
#define HHI      (OFF_A)              // overlay after GEMM1
#define HLO      (OFF_A + 32768)
#define OFF_VS   (OFF_A)              // overlay after GEMM2 (70144 B)
#define OFF_B    (OFF_A + 65536)      // 80 KB region
#define W1HI     (OFF_B)              // 128k x 256B (128 n bf16)
#define W1LO     (OFF_B + 32768)
#define W2HI     (OFF_B)              // overlay: 128k x 320B (144 n bf16)
#define W2LO     (OFF_B + 40960)
#define SMEM_BYTES (OFF_B + 81920)    // 149504

// ---- pre-converted weights (swizzled, byte-identical to smem layouts) ----
__device__ __align__(16) unsigned char g_w1hi[256 * 256];   // [256k][256B]
__device__ __align__(16) unsigned char g_w1lo[256 * 256];
__device__ __align__(16) unsigned char g_w2hi[128 * 320];   // [128k][320B], n->144 pad
__device__ __align__(16) unsigned char g_w2lo[128 * 320];

static __device__ __forceinline__ uint32_t smem_u32(const void* p) {
    uint32_t a;
    asm("{ .reg .u64 t; cvta.to.shared.u64 t, %1; cvt.u32.u64 %0, t; }"
        : "=r"(a) : "l"(p));
    return a;
}

static __device__ __forceinline__ uint32_t swz256(int row, int bc) {
    return (uint32_t)(row * 256 + ((((bc >> 4) ^ (row & 7)) << 4) | (bc & 15)));
}
static __device__ __forceinline__ uint32_t swz320(int row, int bc) {
    int c = bc >> 4;
    if (c < 16) c ^= (row & 7);
    return (uint32_t)(row * 320 + (c << 4) + (bc & 15));
}
static __device__ __forceinline__ uint32_t lm256(uint32_t base, int r0, int bc0, int lane) {
    int row = r0 + (lane & 15), bc = bc0 + ((lane >> 4) << 4);
    return base + swz256(row, bc);
}
static __device__ __forceinline__ uint32_t lm320(uint32_t base, int r0, int bc0, int lane) {
    int row = r0 + (lane & 15), bc = bc0 + ((lane >> 4) << 4);
    return base + swz320(row, bc);
}

static __device__ __forceinline__ void ldsm_x4(uint32_t a, uint32_t r[4]) {
    asm volatile("ldmatrix.sync.aligned.m8n8.x4.shared.b16 {%0,%1,%2,%3}, [%4];"
                 : "=r"(r[0]), "=r"(r[1]), "=r"(r[2]), "=r"(r[3]) : "r"(a));
}
static __device__ __forceinline__ void ldsm_x4t(uint32_t a, uint32_t r[4]) {
    asm volatile("ldmatrix.sync.aligned.m8n8.x4.trans.shared.b16 {%0,%1,%2,%3}, [%4];"
                 : "=r"(r[0]), "=r"(r[1]), "=r"(r[2]), "=r"(r[3]) : "r"(a));
}
static __device__ __forceinline__ void ldsm_x2t(uint32_t a, uint32_t r[2]) {
    asm volatile("ldmatrix.sync.aligned.m8n8.x2.trans.shared.b16 {%0,%1}, [%2];"
                 : "=r"(r[0]), "=r"(r[1]) : "r"(a));
}
static __device__ __forceinline__ void mma_bf16(float d[4], const uint32_t a[4],
                                                const uint32_t* b) {
    asm volatile(
        "mma.sync.aligned.m16n8k16.row.col.f32.bf16.bf16.f32 "
        "{%0,%1,%2,%3}, {%4,%5,%6,%7}, {%8,%9}, {%0,%1,%2,%3};"
        : "+f"(d[0]), "+f"(d[1]), "+f"(d[2]), "+f"(d[3])
        : "r"(a[0]), "r"(a[1]), "r"(a[2]), "r"(a[3]), "r"(b[0]), "r"(b[1]));
}

#define CP16(dst, src) \
    asm volatile("cp.async.cg.shared.global [%0], [%1], 16;" :: "r"(dst), "l"(src))
#define CP_COMMIT() asm volatile("cp.async.commit_group;" ::: "memory")
#define CP_WAIT0()  asm volatile("cp.async.wait_group 0;" ::: "memory")

static __device__ __forceinline__ uint32_t bf2u(__nv_bfloat162 v) {
    return *reinterpret_cast<uint32_t*>(&v);
}
static __device__ __forceinline__ void split8(const float* v, uint4& h, uint4& l) {
    uint32_t hp[4], lp[4];
#pragma unroll
    for (int q = 0; q < 4; q++) {
        float a = v[2*q], b = v[2*q+1];
        __nv_bfloat162 hh = __floats2bfloat162_rn(a, b);
        float ra = a - __bfloat162float(__low2bfloat16(hh));
        float rb = b - __bfloat162float(__high2bfloat16(hh));
        __nv_bfloat162 ll = __floats2bfloat162_rn(ra, rb);
        hp[q] = bf2u(hh); lp[q] = bf2u(ll);
    }
    h = make_uint4(hp[0], hp[1], hp[2], hp[3]);
    l = make_uint4(lp[0], lp[1], lp[2], lp[3]);
}

// ---- prep kernel: W1/W2 -> swizzled bf16 hi/lo globals ----
__global__ void prep_weights(const float* __restrict__ W1,
                             const float* __restrict__ W2) {
    int t = blockIdx.x * blockDim.x + threadIdx.x;
    if (t < 32768) {                       // W1: [256k][128n]
        int k = t >> 7, n = t & 127;
        float v = W1[t];
        __nv_bfloat16 h = __float2bfloat16_rn(v);
        __nv_bfloat16 l = __float2bfloat16_rn(v - __bfloat162float(h));
        uint32_t off = (uint32_t)(k * 256 + ((((n >> 3) ^ (k & 7)) << 4) | ((n & 7) * 2)));
        *reinterpret_cast<__nv_bfloat16*>(g_w1hi + off) = h;
        *reinterpret_cast<__nv_bfloat16*>(g_w1lo + off) = l;
    } else if (t < 32768 + 128 * 144) {    // W2: [128k][144n], n>=136 pad zero
        int u = t - 32768;
        int k = u / 144, n = u - k * 144;
        float v = (n < TRIL) ? W2[k * TRIL + n] : 0.f;
        __nv_bfloat16 h = __float2bfloat16_rn(v);
        __nv_bfloat16 l = __float2bfloat16_rn(v - __bfloat162float(h));
        int c = n >> 3; if (c < 16) c ^= (k & 7);
        uint32_t off = (uint32_t)(k * 320 + (c << 4) + ((n & 7) * 2));
        *reinterpret_cast<__nv_bfloat16*>(g_w2hi + off) = h;
        *reinterpret_cast<__nv_bfloat16*>(g_w2lo + off) = l;
    }
}

// ---- stage 3: symmetric rho row ----
template <int I>
static __device__ __forceinline__ void rho_row_sym(const float* __restrict__ vrow,
                                                   float invtr,
                                                   float* __restrict__ orow) {
    constexpr int TI = I * (I + 1) / 2;
    float Li[I + 1];
#pragma unroll
    for (int k = 0; k <= I; k++) Li[k] = vrow[TI + k];
#pragma unroll
    for (int j = 0; j <= I; j++) {
        const int tj = j * (j + 1) / 2;
        float dot = 0.f;
#pragma unroll
        for (int k = 0; k <= j; k++) dot = fmaf(Li[k], vrow[tj + k], dot);
        float val = dot * invtr;
        orow[I * 16 + j] = val;
        if (j < I) orow[j * 16 + I] = val;
    }
}

__global__ void __launch_bounds__(THREADS, 1)
density_mlp_hmma(const float* __restrict__ x,
                 const float* __restrict__ b1,
                 const float* __restrict__ b2,
                 float* __restrict__ out) {
    extern __shared__ char smem[];
    const uint32_t sb = smem_u32(smem);
    const int tid  = threadIdx.x;
    const int wid  = tid >> 5;
    const int lane = tid & 31;
    const int brow = blockIdx.x * 128;

    float* bias1 = reinterpret_cast<float*>(smem + OFF_B1);
    float* bias2 = reinterpret_cast<float*>(smem + OFF_B2);
    float* trc   = reinterpret_cast<float*>(smem + OFF_TR);

    if (tid < 128) { bias1[tid] = b1[tid]; trc[tid] = 0.f; }
    if (tid < TRIL) bias2[tid] = b2[tid];

    const int m0  = (wid >> 1) * 32;      // warp row base
    const int n0g = (wid & 1) * 64;       // warp col base (GEMM1)

    // ======================= GEMM1: 2 K-chunks of 128 =======================
    float acc[2][8][4];
#pragma unroll
    for (int mt = 0; mt < 2; mt++)
#pragma unroll
    for (int nt = 0; nt < 8; nt++)
#pragma unroll
    for (int q = 0; q < 4; q++) acc[mt][nt][q] = 0.f;

    for (int c = 0; c < 2; c++) {
        if (c) __syncthreads();           // warps done with previous chunk smem
        // W1 chunk: bare cp.async copies of pre-swizzled slabs (no live regs)
        {
            const unsigned char* sh = g_w1hi + c * 32768;
            const unsigned char* sl = g_w1lo + c * 32768;
#pragma unroll
            for (int i = 0; i < 8; i++) {
                int u = (tid + i * THREADS) * 16;    // 0..32752
                CP16(sb + W1HI + u, sh + u);
                CP16(sb + W1LO + u, sl + u);
            }
            CP_COMMIT();
        }
        // X chunk [128r x 128k] -> XHI/XLO (fp32 load + split, as round 4)
#pragma unroll
        for (int i = 0; i < 8; i++) {
            int u = tid + i * THREADS;    // 0..2047
            int row = u >> 4, j = u & 15;
            const float* s = x + (size_t)(brow + row) * 256 + c * 128 + j * 8;
            float4 p = *reinterpret_cast<const float4*>(s);
            float4 q4 = *reinterpret_cast<const float4*>(s + 4);
            float v[8] = {p.x, p.y, p.z, p.w, q4.x, q4.y, q4.z, q4.w};
            uint4 h, l; split8(v, h, l);
            uint32_t off = swz256(row, j * 16);
            *reinterpret_cast<uint4*>(smem + XHI + off) = h;
            *reinterpret_cast<uint4*>(smem + XLO + off) = l;
        }
        CP_WAIT0();
        __syncthreads();

#pragma unroll
        for (int kt = 0; kt < 8; kt++) {
            uint32_t ah[2][4], al[2][4];
            ldsm_x4(lm256(sb + XHI, m0,      kt * 32, lane), ah[0]);
            ldsm_x4(lm256(sb + XHI, m0 + 16, kt * 32, lane), ah[1]);
            ldsm_x4(lm256(sb + XLO, m0,      kt * 32, lane), al[0]);
            ldsm_x4(lm256(sb + XLO, m0 + 16, kt * 32, lane), al[1]);
#pragma unroll
            for (int p = 0; p < 4; p++) {
                uint32_t th[4], tl[4];
                ldsm_x4t(lm256(sb + W1HI, kt * 16, (n0g + p * 16) * 2, lane), th);
                ldsm_x4t(lm256(sb + W1LO, kt * 16, (n0g + p * 16) * 2, lane), tl);
#pragma unroll
                for (int mt = 0; mt < 2; mt++) {
                    mma_bf16(acc[mt][2*p],   ah[mt], th);
                    mma_bf16(acc[mt][2*p],   ah[mt], tl);
                    mma_bf16(acc[mt][2*p],   al[mt], th);
                    mma_bf16(acc[mt][2*p+1], ah[mt], th + 2);
                    mma_bf16(acc[mt][2*p+1], ah[mt], tl + 2);
                    mma_bf16(acc[mt][2*p+1], al[mt], th + 2);
                }
            }
        }
    }
    __syncthreads();                      // GEMM1 done; A/B regions reusable

    // ============== epilogue 1: H = relu(C1+b1) -> HHI/HLO ==================
    // W2 copy first: bare cp.async overlaps with the epilogue math below
    {
#pragma unroll
        for (int i = 0; i < 10; i++) {
            int u = (tid + i * THREADS) * 16;        // 0..40944
            CP16(sb + W2HI + u, g_w2hi + u);
            CP16(sb + W2LO + u, g_w2lo + u);
        }
        CP_COMMIT();
    }
#pragma unroll
    for (int mt = 0; mt < 2; mt++)
#pragma unroll
    for (int nt = 0; nt < 8; nt++) {
        int col = n0g + nt * 8 + ((lane & 3) << 1);
        float ba = bias1[col], bb = bias1[col + 1];
        int r = m0 + mt * 16 + (lane >> 2);
#pragma unroll
        for (int half = 0; half < 2; half++) {
            float v0 = fmaxf(acc[mt][nt][2*half]     + ba, 0.f);
            float v1 = fmaxf(acc[mt][nt][2*half + 1] + bb, 0.f);
            __nv_bfloat162 hh = __floats2bfloat162_rn(v0, v1);
            float r0 = v0 - __bfloat162float(__low2bfloat16(hh));
            float r1 = v1 - __bfloat162float(__high2bfloat16(hh));
            __nv_bfloat162 ll = __floats2bfloat162_rn(r0, r1);
            uint32_t off = swz256(r + half * 8, col * 2);
            *reinterpret_cast<uint32_t*>(smem + HHI + off) = bf2u(hh);
            *reinterpret_cast<uint32_t*>(smem + HLO + off) = bf2u(ll);
        }
    }
    CP_WAIT0();
    __syncthreads();

    // ========================== GEMM2: H @ W2 ===============================
    const int n0g2 = (wid & 1) * 72;
    float acc2[2][9][4];
#pragma unroll
    for (int mt = 0; mt < 2; mt++)
#pragma unroll
    for (int nt = 0; nt < 9; nt++)
#pragma unroll
    for (int q = 0; q < 4; q++) acc2[mt][nt][q] = 0.f;

#pragma unroll
    for (int kt = 0; kt < 8; kt++) {
        uint32_t ah[2][4], al[2][4];
        ldsm_x4(lm256(sb + HHI, m0,      kt * 32, lane), ah[0]);
        ldsm_x4(lm256(sb + HHI, m0 + 16, kt * 32, lane), ah[1]);
        ldsm_x4(lm256(sb + HLO, m0,      kt * 32, lane), al[0]);
        ldsm_x4(lm256(sb + HLO, m0 + 16, kt * 32, lane), al[1]);
#pragma unroll
        for (int p = 0; p < 4; p++) {
            uint32_t th[4], tl[4];
            ldsm_x4t(lm320(sb + W2HI, kt * 16, (n0g2 + p * 16) * 2, lane), th);
            ldsm_x4t(lm320(sb + W2LO, kt * 16, (n0g2 + p * 16) * 2, lane), tl);
#pragma unroll
            for (int mt = 0; mt < 2; mt++) {
                mma_bf16(acc2[mt][2*p],   ah[mt], th);
                mma_bf16(acc2[mt][2*p],   ah[mt], tl);
                mma_bf16(acc2[mt][2*p],   al[mt], th);
                mma_bf16(acc2[mt][2*p+1], ah[mt], th + 2);
                mma_bf16(acc2[mt][2*p+1], ah[mt], tl + 2);
                mma_bf16(acc2[mt][2*p+1], al[mt], th + 2);
            }
        }
        {
            uint32_t bh8[2], bl8[2];
            ldsm_x2t(lm320(sb + W2HI, kt * 16, (n0g2 + 64) * 2, lane), bh8);
            ldsm_x2t(lm320(sb + W2LO, kt * 16, (n0g2 + 64) * 2, lane), bl8);
#pragma unroll
            for (int mt = 0; mt < 2; mt++) {
                mma_bf16(acc2[mt][8], ah[mt], bh8);
                mma_bf16(acc2[mt][8], ah[mt], bl8);
                mma_bf16(acc2[mt][8], al[mt], bh8);
            }
        }
    }
    __syncthreads();                      // H/W2 regions reusable (Vs overlay)

    // ============ epilogue 2: V = C2+b2 -> Vs, trace ========================
    {
        float* Vs = reinterpret_cast<float*>(smem + OFF_VS);
        float part[2][2] = {{0.f, 0.f}, {0.f, 0.f}};
#pragma unroll
        for (int mt = 0; mt < 2; mt++)
#pragma unroll
        for (int nt = 0; nt < 9; nt++) {
            int col = n0g2 + nt * 8 + ((lane & 3) << 1);
            if (col < TRIL) {
                float ba = bias2[col];
                float bb = (col + 1 < TRIL) ? bias2[col + 1] : 0.f;
                int r = m0 + mt * 16 + (lane >> 2);
#pragma unroll
                for (int half = 0; half < 2; half++) {
                    float v0 = acc2[mt][nt][2*half] + ba;
                    Vs[(r + half*8) * VS_STRIDE + col] = v0;
                    part[mt][half] = fmaf(v0, v0, part[mt][half]);
                    if (col + 1 < TRIL) {
                        float v1 = acc2[mt][nt][2*half + 1] + bb;
                        Vs[(r + half*8) * VS_STRIDE + col + 1] = v1;
                        part[mt][half] = fmaf(v1, v1, part[mt][half]);
                    }
                }
            }
        }
        // reduce across the 4 lanes sharing a row (lane&3), then one atomic
#pragma unroll
        for (int mt = 0; mt < 2; mt++)
#pragma unroll
        for (int half = 0; half < 2; half++) {
            float s = part[mt][half];
            s += __shfl_xor_sync(0xFFFFFFFF, s, 1);
            s += __shfl_xor_sync(0xFFFFFFFF, s, 2);
            if ((lane & 3) == 0)
                atomicAdd(&trc[m0 + mt * 16 + (lane >> 2) + half * 8], s);
        }
    }
    __syncthreads();

    // ============== stage 3: rho = L L^T / trace (symmetric) ================
    {
        const float* Vs = reinterpret_cast<const float*>(smem + OFF_VS);
        const int row = tid & 127;
        const int ib  = tid >> 7;
        const float* vrow = &Vs[row * VS_STRIDE];
        const float invtr = 1.0f / trc[row];
        float* orow = &out[(size_t)(brow + row) * 256];
        if (ib == 0) {
            rho_row_sym<0>(vrow, invtr, orow);  rho_row_sym<2>(vrow, invtr, orow);
            rho_row_sym<4>(vrow, invtr, orow);  rho_row_sym<6>(vrow, invtr, orow);
            rho_row_sym<8>(vrow, invtr, orow);  rho_row_sym<10>(vrow, invtr, orow);
            rho_row_sym<12>(vrow, invtr, orow); rho_row_sym<14>(vrow, invtr, orow);
        } else {
            rho_row_sym<1>(vrow, invtr, orow);  rho_row_sym<3>(vrow, invtr, orow);
            rho_row_sym<5>(vrow, invtr, orow);  rho_row_sym<7>(vrow, invtr, orow);
            rho_row_sym<9>(vrow, invtr, orow);  rho_row_sym<11>(vrow, invtr, orow);
            rho_row_sym<13>(vrow, invtr, orow); rho_row_sym<15>(vrow, invtr, orow);
        }
    }
}

extern "C" void kernel_launch(void* const* d_in, const int* in_sizes, int n_in,
                              void* d_out, int out_size) {
    const float* x  = (const float*)d_in[0];
    const float* W1 = (const float*)d_in[1];
    const float* b1 = (const float*)d_in[2];
    const float* W2 = (const float*)d_in[3];
    const float* b2 = (const float*)d_in[4];
    float* out = (float*)d_out;

    const int batch  = in_sizes[0] / 256;   // 131072
    const int blocks = batch / 128;         // 1024

    prep_weights<<<200, 256>>>(W1, W2);

    cudaFuncSetAttribute(density_mlp_hmma,
                         cudaFuncAttributeMaxDynamicSharedMemorySize, SMEM_BYTES);
    density_mlp_hmma<<<blocks, THREADS, SMEM_BYTES>>>(x, b1, b2, out);
}

// round 9
// speedup vs baseline: 1.7291x; 1.5959x over previous
#include <cuda_runtime.h>
#include <cuda_bf16.h>
#include <cstdint>

// ===========================================================================
// DensityMatrixMLP, fused bf16 split-precision mma.sync (HMMA), round 8.
// = round 4 structure + pre-swizzled cp.async weights + shfl trace reduce.
// Stage 3 is round-4's vectorized rho_row (float4 stores) — the round-5/6/7
// "symmetric" scalar-store variant caused 3.4x L2 transaction amplification.
// ===========================================================================

#define THREADS 256
#define TRIL    136
#define VS_STRIDE 137

// ---- smem layout (bytes) ---- (identical to round 4)
#define OFF_B1   0            // 128 f32
#define OFF_B2   512          // 136 f32
#define OFF_TR   1088         // 128 f32
#define OFF_A    2048         // 64 KB region
#define XHI      (OFF_A)              // 128r x 256B (128 k bf16)
#define XLO      (OFF_A + 32768)
#define HHI      (OFF_A)              // overlay after GEMM1
#define HLO      (OFF_A + 32768)
#define OFF_VS   (OFF_A)              // overlay after GEMM2 (70144 B)
#define OFF_B    (OFF_A + 65536)      // 80 KB region
#define W1HI     (OFF_B)              // 128k x 256B (128 n bf16)
#define W1LO     (OFF_B + 32768)
#define W2HI     (OFF_B)              // overlay: 128k x 320B (144 n bf16)
#define W2LO     (OFF_B + 40960)
#define SMEM_BYTES (OFF_B + 81920)    // 149504

// ---- pre-converted weights (swizzled, byte-identical to smem layouts) ----
__device__ __align__(16) unsigned char g_w1hi[256 * 256];   // [256k][256B]
__device__ __align__(16) unsigned char g_w1lo[256 * 256];
__device__ __align__(16) unsigned char g_w2hi[128 * 320];   // [128k][320B], n->144 pad
__device__ __align__(16) unsigned char g_w2lo[128 * 320];

static __device__ __forceinline__ uint32_t smem_u32(const void* p) {
    uint32_t a;
    asm("{ .reg .u64 t; cvta.to.shared.u64 t, %1; cvt.u32.u64 %0, t; }"
        : "=r"(a) : "l"(p));
    return a;
}

static __device__ __forceinline__ uint32_t swz256(int row, int bc) {
    return (uint32_t)(row * 256 + ((((bc >> 4) ^ (row & 7)) << 4) | (bc & 15)));
}
static __device__ __forceinline__ uint32_t swz320(int row, int bc) {
    int c = bc >> 4;
    if (c < 16) c ^= (row & 7);
    return (uint32_t)(row * 320 + (c << 4) + (bc & 15));
}
static __device__ __forceinline__ uint32_t lm256(uint32_t base, int r0, int bc0, int lane) {
    int row = r0 + (lane & 15), bc = bc0 + ((lane >> 4) << 4);
    return base + swz256(row, bc);
}
static __device__ __forceinline__ uint32_t lm320(uint32_t base, int r0, int bc0, int lane) {
    int row = r0 + (lane & 15), bc = bc0 + ((lane >> 4) << 4);
    return base + swz320(row, bc);
}

static __device__ __forceinline__ void ldsm_x4(uint32_t a, uint32_t r[4]) {
    asm volatile("ldmatrix.sync.aligned.m8n8.x4.shared.b16 {%0,%1,%2,%3}, [%4];"
                 : "=r"(r[0]), "=r"(r[1]), "=r"(r[2]), "=r"(r[3]) : "r"(a));
}
static __device__ __forceinline__ void ldsm_x4t(uint32_t a, uint32_t r[4]) {
    asm volatile("ldmatrix.sync.aligned.m8n8.x4.trans.shared.b16 {%0,%1,%2,%3}, [%4];"
                 : "=r"(r[0]), "=r"(r[1]), "=r"(r[2]), "=r"(r[3]) : "r"(a));
}
static __device__ __forceinline__ void ldsm_x2t(uint32_t a, uint32_t r[2]) {
    asm volatile("ldmatrix.sync.aligned.m8n8.x2.trans.shared.b16 {%0,%1}, [%2];"
                 : "=r"(r[0]), "=r"(r[1]) : "r"(a));
}
static __device__ __forceinline__ void mma_bf16(float d[4], const uint32_t a[4],
                                                const uint32_t* b) {
    asm volatile(
        "mma.sync.aligned.m16n8k16.row.col.f32.bf16.bf16.f32 "
        "{%0,%1,%2,%3}, {%4,%5,%6,%7}, {%8,%9}, {%0,%1,%2,%3};"
        : "+f"(d[0]), "+f"(d[1]), "+f"(d[2]), "+f"(d[3])
        : "r"(a[0]), "r"(a[1]), "r"(a[2]), "r"(a[3]), "r"(b[0]), "r"(b[1]));
}

#define CP16(dst, src) \
    asm volatile("cp.async.cg.shared.global [%0], [%1], 16;" :: "r"(dst), "l"(src))
#define CP_COMMIT() asm volatile("cp.async.commit_group;" ::: "memory")
#define CP_WAIT0()  asm volatile("cp.async.wait_group 0;" ::: "memory")

static __device__ __forceinline__ uint32_t bf2u(__nv_bfloat162 v) {
    return *reinterpret_cast<uint32_t*>(&v);
}
static __device__ __forceinline__ void split8(const float* v, uint4& h, uint4& l) {
    uint32_t hp[4], lp[4];
#pragma unroll
    for (int q = 0; q < 4; q++) {
        float a = v[2*q], b = v[2*q+1];
        __nv_bfloat162 hh = __floats2bfloat162_rn(a, b);
        float ra = a - __bfloat162float(__low2bfloat16(hh));
        float rb = b - __bfloat162float(__high2bfloat16(hh));
        __nv_bfloat162 ll = __floats2bfloat162_rn(ra, rb);
        hp[q] = bf2u(hh); lp[q] = bf2u(ll);
    }
    h = make_uint4(hp[0], hp[1], hp[2], hp[3]);
    l = make_uint4(lp[0], lp[1], lp[2], lp[3]);
}

// ---- prep kernel: W1/W2 -> swizzled bf16 hi/lo globals ----
__global__ void prep_weights(const float* __restrict__ W1,
                             const float* __restrict__ W2) {
    int t = blockIdx.x * blockDim.x + threadIdx.x;
    if (t < 32768) {                       // W1: [256k][128n]
        int k = t >> 7, n = t & 127;
        float v = W1[t];
        __nv_bfloat16 h = __float2bfloat16_rn(v);
        __nv_bfloat16 l = __float2bfloat16_rn(v - __bfloat162float(h));
        uint32_t off = (uint32_t)(k * 256 + ((((n >> 3) ^ (k & 7)) << 4) | ((n & 7) * 2)));
        *reinterpret_cast<__nv_bfloat16*>(g_w1hi + off) = h;
        *reinterpret_cast<__nv_bfloat16*>(g_w1lo + off) = l;
    } else if (t < 32768 + 128 * 144) {    // W2: [128k][144n], n>=136 pad zero
        int u = t - 32768;
        int k = u / 144, n = u - k * 144;
        float v = (n < TRIL) ? W2[k * TRIL + n] : 0.f;
        __nv_bfloat16 h = __float2bfloat16_rn(v);
        __nv_bfloat16 l = __float2bfloat16_rn(v - __bfloat162float(h));
        int c = n >> 3; if (c < 16) c ^= (k & 7);
        uint32_t off = (uint32_t)(k * 320 + (c << 4) + ((n & 7) * 2));
        *reinterpret_cast<__nv_bfloat16*>(g_w2hi + off) = h;
        *reinterpret_cast<__nv_bfloat16*>(g_w2lo + off) = l;
    }
}

// ---- stage 3: round-4 rho row (min(i,j)-length dots, float4 stores) ----
template <int I>
static __device__ __forceinline__ void rho_row(const float* __restrict__ vrow,
                                               float invtr,
                                               float* __restrict__ orow) {
    constexpr int TI = I * (I + 1) / 2;
    float Li[I + 1];
#pragma unroll
    for (int k = 0; k <= I; k++) Li[k] = vrow[TI + k];
    float res[16];
#pragma unroll
    for (int j = 0; j < 16; j++) {
        const int tj = j * (j + 1) / 2;
        const int len = (j < I) ? j : I;
        float dot = 0.f;
#pragma unroll
        for (int k = 0; k <= len; k++) dot = fmaf(Li[k], vrow[tj + k], dot);
        res[j] = dot * invtr;
    }
#pragma unroll
    for (int q = 0; q < 4; q++)
        *reinterpret_cast<float4*>(&orow[I * 16 + 4 * q]) =
            make_float4(res[4*q], res[4*q+1], res[4*q+2], res[4*q+3]);
}

__global__ void __launch_bounds__(THREADS, 1)
density_mlp_hmma(const float* __restrict__ x,
                 const float* __restrict__ b1,
                 const float* __restrict__ b2,
                 float* __restrict__ out) {
    extern __shared__ char smem[];
    const uint32_t sb = smem_u32(smem);
    const int tid  = threadIdx.x;
    const int wid  = tid >> 5;
    const int lane = tid & 31;
    const int brow = blockIdx.x * 128;

    float* bias1 = reinterpret_cast<float*>(smem + OFF_B1);
    float* bias2 = reinterpret_cast<float*>(smem + OFF_B2);
    float* trc   = reinterpret_cast<float*>(smem + OFF_TR);

    if (tid < 128) { bias1[tid] = b1[tid]; trc[tid] = 0.f; }
    if (tid < TRIL) bias2[tid] = b2[tid];

    const int m0  = (wid >> 1) * 32;      // warp row base
    const int n0g = (wid & 1) * 64;       // warp col base (GEMM1)

    // ======================= GEMM1: 2 K-chunks of 128 =======================
    float acc[2][8][4];
#pragma unroll
    for (int mt = 0; mt < 2; mt++)
#pragma unroll
    for (int nt = 0; nt < 8; nt++)
#pragma unroll
    for (int q = 0; q < 4; q++) acc[mt][nt][q] = 0.f;

    for (int c = 0; c < 2; c++) {
        if (c) __syncthreads();           // warps done with previous chunk smem
        // W1 chunk: bare cp.async copies of pre-swizzled slabs
        {
            const unsigned char* sh = g_w1hi + c * 32768;
            const unsigned char* sl = g_w1lo + c * 32768;
#pragma unroll
            for (int i = 0; i < 8; i++) {
                int u = (tid + i * THREADS) * 16;    // 0..32752
                CP16(sb + W1HI + u, sh + u);
                CP16(sb + W1LO + u, sl + u);
            }
            CP_COMMIT();
        }
        // X chunk [128r x 128k] -> XHI/XLO (fp32 load + split)
#pragma unroll
        for (int i = 0; i < 8; i++) {
            int u = tid + i * THREADS;    // 0..2047
            int row = u >> 4, j = u & 15;
            const float* s = x + (size_t)(brow + row) * 256 + c * 128 + j * 8;
            float4 p = *reinterpret_cast<const float4*>(s);
            float4 q4 = *reinterpret_cast<const float4*>(s + 4);
            float v[8] = {p.x, p.y, p.z, p.w, q4.x, q4.y, q4.z, q4.w};
            uint4 h, l; split8(v, h, l);
            uint32_t off = swz256(row, j * 16);
            *reinterpret_cast<uint4*>(smem + XHI + off) = h;
            *reinterpret_cast<uint4*>(smem + XLO + off) = l;
        }
        CP_WAIT0();
        __syncthreads();

#pragma unroll
        for (int kt = 0; kt < 8; kt++) {
            uint32_t ah[2][4], al[2][4];
            ldsm_x4(lm256(sb + XHI, m0,      kt * 32, lane), ah[0]);
            ldsm_x4(lm256(sb + XHI, m0 + 16, kt * 32, lane), ah[1]);
            ldsm_x4(lm256(sb + XLO, m0,      kt * 32, lane), al[0]);
            ldsm_x4(lm256(sb + XLO, m0 + 16, kt * 32, lane), al[1]);
#pragma unroll
            for (int p = 0; p < 4; p++) {
                uint32_t th[4], tl[4];
                ldsm_x4t(lm256(sb + W1HI, kt * 16, (n0g + p * 16) * 2, lane), th);
                ldsm_x4t(lm256(sb + W1LO, kt * 16, (n0g + p * 16) * 2, lane), tl);
#pragma unroll
                for (int mt = 0; mt < 2; mt++) {
                    mma_bf16(acc[mt][2*p],   ah[mt], th);
                    mma_bf16(acc[mt][2*p],   ah[mt], tl);
                    mma_bf16(acc[mt][2*p],   al[mt], th);
                    mma_bf16(acc[mt][2*p+1], ah[mt], th + 2);
                    mma_bf16(acc[mt][2*p+1], ah[mt], tl + 2);
                    mma_bf16(acc[mt][2*p+1], al[mt], th + 2);
                }
            }
        }
    }
    __syncthreads();                      // GEMM1 done; A/B regions reusable

    // ============== epilogue 1: H = relu(C1+b1) -> HHI/HLO ==================
    // W2 copy first: bare cp.async overlaps with the epilogue math below
    {
#pragma unroll
        for (int i = 0; i < 10; i++) {
            int u = (tid + i * THREADS) * 16;        // 0..40944
            CP16(sb + W2HI + u, g_w2hi + u);
            CP16(sb + W2LO + u, g_w2lo + u);
        }
        CP_COMMIT();
    }
#pragma unroll
    for (int mt = 0; mt < 2; mt++)
#pragma unroll
    for (int nt = 0; nt < 8; nt++) {
        int col = n0g + nt * 8 + ((lane & 3) << 1);
        float ba = bias1[col], bb = bias1[col + 1];
        int r = m0 + mt * 16 + (lane >> 2);
#pragma unroll
        for (int half = 0; half < 2; half++) {
            float v0 = fmaxf(acc[mt][nt][2*half]     + ba, 0.f);
            float v1 = fmaxf(acc[mt][nt][2*half + 1] + bb, 0.f);
            __nv_bfloat162 hh = __floats2bfloat162_rn(v0, v1);
            float r0 = v0 - __bfloat162float(__low2bfloat16(hh));
            float r1 = v1 - __bfloat162float(__high2bfloat16(hh));
            __nv_bfloat162 ll = __floats2bfloat162_rn(r0, r1);
            uint32_t off = swz256(r + half * 8, col * 2);
            *reinterpret_cast<uint32_t*>(smem + HHI + off) = bf2u(hh);
            *reinterpret_cast<uint32_t*>(smem + HLO + off) = bf2u(ll);
        }
    }
    CP_WAIT0();
    __syncthreads();

    // ========================== GEMM2: H @ W2 ===============================
    const int n0g2 = (wid & 1) * 72;
    float acc2[2][9][4];
#pragma unroll
    for (int mt = 0; mt < 2; mt++)
#pragma unroll
    for (int nt = 0; nt < 9; nt++)
#pragma unroll
    for (int q = 0; q < 4; q++) acc2[mt][nt][q] = 0.f;

#pragma unroll
    for (int kt = 0; kt < 8; kt++) {
        uint32_t ah[2][4], al[2][4];
        ldsm_x4(lm256(sb + HHI, m0,      kt * 32, lane), ah[0]);
        ldsm_x4(lm256(sb + HHI, m0 + 16, kt * 32, lane), ah[1]);
        ldsm_x4(lm256(sb + HLO, m0,      kt * 32, lane), al[0]);
        ldsm_x4(lm256(sb + HLO, m0 + 16, kt * 32, lane), al[1]);
#pragma unroll
        for (int p = 0; p < 4; p++) {
            uint32_t th[4], tl[4];
            ldsm_x4t(lm320(sb + W2HI, kt * 16, (n0g2 + p * 16) * 2, lane), th);
            ldsm_x4t(lm320(sb + W2LO, kt * 16, (n0g2 + p * 16) * 2, lane), tl);
#pragma unroll
            for (int mt = 0; mt < 2; mt++) {
                mma_bf16(acc2[mt][2*p],   ah[mt], th);
                mma_bf16(acc2[mt][2*p],   ah[mt], tl);
                mma_bf16(acc2[mt][2*p],   al[mt], th);
                mma_bf16(acc2[mt][2*p+1], ah[mt], th + 2);
                mma_bf16(acc2[mt][2*p+1], ah[mt], tl + 2);
                mma_bf16(acc2[mt][2*p+1], al[mt], th + 2);
            }
        }
        {
            uint32_t bh8[2], bl8[2];
            ldsm_x2t(lm320(sb + W2HI, kt * 16, (n0g2 + 64) * 2, lane), bh8);
            ldsm_x2t(lm320(sb + W2LO, kt * 16, (n0g2 + 64) * 2, lane), bl8);
#pragma unroll
            for (int mt = 0; mt < 2; mt++) {
                mma_bf16(acc2[mt][8], ah[mt], bh8);
                mma_bf16(acc2[mt][8], ah[mt], bl8);
                mma_bf16(acc2[mt][8], al[mt], bh8);
            }
        }
    }
    __syncthreads();                      // H/W2 regions reusable (Vs overlay)

    // ============ epilogue 2: V = C2+b2 -> Vs, trace ========================
    {
        float* Vs = reinterpret_cast<float*>(smem + OFF_VS);
        float part[2][2] = {{0.f, 0.f}, {0.f, 0.f}};
#pragma unroll
        for (int mt = 0; mt < 2; mt++)
#pragma unroll
        for (int nt = 0; nt < 9; nt++) {
            int col = n0g2 + nt * 8 + ((lane & 3) << 1);
            if (col < TRIL) {
                float ba = bias2[col];
                float bb = (col + 1 < TRIL) ? bias2[col + 1] : 0.f;
                int r = m0 + mt * 16 + (lane >> 2);
#pragma unroll
                for (int half = 0; half < 2; half++) {
                    float v0 = acc2[mt][nt][2*half] + ba;
                    Vs[(r + half*8) * VS_STRIDE + col] = v0;
                    part[mt][half] = fmaf(v0, v0, part[mt][half]);
                    if (col + 1 < TRIL) {
                        float v1 = acc2[mt][nt][2*half + 1] + bb;
                        Vs[(r + half*8) * VS_STRIDE + col + 1] = v1;
                        part[mt][half] = fmaf(v1, v1, part[mt][half]);
                    }
                }
            }
        }
        // reduce across the 4 lanes sharing a row, then one atomic
#pragma unroll
        for (int mt = 0; mt < 2; mt++)
#pragma unroll
        for (int half = 0; half < 2; half++) {
            float s = part[mt][half];
            s += __shfl_xor_sync(0xFFFFFFFF, s, 1);
            s += __shfl_xor_sync(0xFFFFFFFF, s, 2);
            if ((lane & 3) == 0)
                atomicAdd(&trc[m0 + mt * 16 + (lane >> 2) + half * 8], s);
        }
    }
    __syncthreads();

    // ===================== stage 3: rho = L L^T / trace =====================
    {
        const float* Vs = reinterpret_cast<const float*>(smem + OFF_VS);
        const int row = tid & 127;
        const int ib  = tid >> 7;
        const float* vrow = &Vs[row * VS_STRIDE];
        const float invtr = 1.0f / trc[row];
        float* orow = &out[(size_t)(brow + row) * 256];
        if (ib == 0) {
            rho_row<0>(vrow, invtr, orow);  rho_row<2>(vrow, invtr, orow);
            rho_row<4>(vrow, invtr, orow);  rho_row<6>(vrow, invtr, orow);
            rho_row<8>(vrow, invtr, orow);  rho_row<10>(vrow, invtr, orow);
            rho_row<12>(vrow, invtr, orow); rho_row<14>(vrow, invtr, orow);
        } else {
            rho_row<1>(vrow, invtr, orow);  rho_row<3>(vrow, invtr, orow);
            rho_row<5>(vrow, invtr, orow);  rho_row<7>(vrow, invtr, orow);
            rho_row<9>(vrow, invtr, orow);  rho_row<11>(vrow, invtr, orow);
            rho_row<13>(vrow, invtr, orow); rho_row<15>(vrow, invtr, orow);
        }
    }
}

extern "C" void kernel_launch(void* const* d_in, const int* in_sizes, int n_in,
                              void* d_out, int out_size) {
    const float* x  = (const float*)d_in[0];
    const float* W1 = (const float*)d_in[1];
    const float* b1 = (const float*)d_in[2];
    const float* W2 = (const float*)d_in[3];
    const float* b2 = (const float*)d_in[4];
    float* out = (float*)d_out;

    const int batch  = in_sizes[0] / 256;   // 131072
    const int blocks = batch / 128;         // 1024

    prep_weights<<<200, 256>>>(W1, W2);

    cudaFuncSetAttribute(density_mlp_hmma,
                         cudaFuncAttributeMaxDynamicSharedMemorySize, SMEM_BYTES);
    density_mlp_hmma<<<blocks, THREADS, SMEM_BYTES>>>(x, b1, b2, out);
}

// round 10
// speedup vs baseline: 1.8942x; 1.0954x over previous
#include <cuda_runtime.h>
#include <cuda_bf16.h>
#include <cstdint>

// ===========================================================================
// DensityMatrixMLP, fused bf16 split-precision mma.sync (HMMA), round 9.
// = round 8, restructured to 64-row CTAs / 128 threads / 4 warps so TWO CTAs
// co-reside per SM (regs 2*128*~210 < 64K, smem ~98KB*2 < 228KB) and overlap
// each other's serialized phases. Per-warp tiles byte-identical to round 8.
// ===========================================================================

#define THREADS 128
#define ROWS    64
#define TRIL    136
#define VS_STRIDE 137

// ---- smem layout (bytes) ----
#define OFF_B1   0            // 128 f32
#define OFF_B2   512          // 136 f32
#define OFF_TR   1088         // 64 f32
#define OFF_A    2048         // 32 KB region (X / H, 64 rows)
#define XHI      (OFF_A)              // 64r x 256B
#define XLO      (OFF_A + 16384)
#define HHI      (OFF_A)              // overlay after GEMM1
#define HLO      (OFF_A + 16384)
#define OFF_W    (OFF_A + 32768)      // 64 KB weight region
#define W1HI     (OFF_W)              // 128k x 256B
#define W1LO     (OFF_W + 32768)
#define W2HI     (OFF_W)              // overlay: 64k x 320B per chunk
#define W2LO     (OFF_W + 20480)
#define OFF_VS   (OFF_A)              // Vs overlay: 64 x 137 f32 = 35072 B
#define SMEM_BYTES (OFF_W + 65536)    // 100352  (2 CTAs/SM: 200704 < 228KB)

// ---- pre-converted weights (swizzled, byte-identical to smem layouts) ----
__device__ __align__(16) unsigned char g_w1hi[256 * 256];   // [256k][256B]
__device__ __align__(16) unsigned char g_w1lo[256 * 256];
__device__ __align__(16) unsigned char g_w2hi[128 * 320];   // [128k][320B], n->144 pad
__device__ __align__(16) unsigned char g_w2lo[128 * 320];

static __device__ __forceinline__ uint32_t smem_u32(const void* p) {
    uint32_t a;
    asm("{ .reg .u64 t; cvta.to.shared.u64 t, %1; cvt.u32.u64 %0, t; }"
        : "=r"(a) : "l"(p));
    return a;
}

static __device__ __forceinline__ uint32_t swz256(int row, int bc) {
    return (uint32_t)(row * 256 + ((((bc >> 4) ^ (row & 7)) << 4) | (bc & 15)));
}
static __device__ __forceinline__ uint32_t swz320(int row, int bc) {
    int c = bc >> 4;
    if (c < 16) c ^= (row & 7);
    return (uint32_t)(row * 320 + (c << 4) + (bc & 15));
}
static __device__ __forceinline__ uint32_t lm256(uint32_t base, int r0, int bc0, int lane) {
    int row = r0 + (lane & 15), bc = bc0 + ((lane >> 4) << 4);
    return base + swz256(row, bc);
}
static __device__ __forceinline__ uint32_t lm320(uint32_t base, int r0, int bc0, int lane) {
    int row = r0 + (lane & 15), bc = bc0 + ((lane >> 4) << 4);
    return base + swz320(row, bc);
}

static __device__ __forceinline__ void ldsm_x4(uint32_t a, uint32_t r[4]) {
    asm volatile("ldmatrix.sync.aligned.m8n8.x4.shared.b16 {%0,%1,%2,%3}, [%4];"
                 : "=r"(r[0]), "=r"(r[1]), "=r"(r[2]), "=r"(r[3]) : "r"(a));
}
static __device__ __forceinline__ void ldsm_x4t(uint32_t a, uint32_t r[4]) {
    asm volatile("ldmatrix.sync.aligned.m8n8.x4.trans.shared.b16 {%0,%1,%2,%3}, [%4];"
                 : "=r"(r[0]), "=r"(r[1]), "=r"(r[2]), "=r"(r[3]) : "r"(a));
}
static __device__ __forceinline__ void ldsm_x2t(uint32_t a, uint32_t r[2]) {
    asm volatile("ldmatrix.sync.aligned.m8n8.x2.trans.shared.b16 {%0,%1}, [%2];"
                 : "=r"(r[0]), "=r"(r[1]) : "r"(a));
}
static __device__ __forceinline__ void mma_bf16(float d[4], const uint32_t a[4],
                                                const uint32_t* b) {
    asm volatile(
        "mma.sync.aligned.m16n8k16.row.col.f32.bf16.bf16.f32 "
        "{%0,%1,%2,%3}, {%4,%5,%6,%7}, {%8,%9}, {%0,%1,%2,%3};"
        : "+f"(d[0]), "+f"(d[1]), "+f"(d[2]), "+f"(d[3])
        : "r"(a[0]), "r"(a[1]), "r"(a[2]), "r"(a[3]), "r"(b[0]), "r"(b[1]));
}

#define CP16(dst, src) \
    asm volatile("cp.async.cg.shared.global [%0], [%1], 16;" :: "r"(dst), "l"(src))
#define CP_COMMIT() asm volatile("cp.async.commit_group;" ::: "memory")
#define CP_WAIT0()  asm volatile("cp.async.wait_group 0;" ::: "memory")

static __device__ __forceinline__ uint32_t bf2u(__nv_bfloat162 v) {
    return *reinterpret_cast<uint32_t*>(&v);
}
static __device__ __forceinline__ void split8(const float* v, uint4& h, uint4& l) {
    uint32_t hp[4], lp[4];
#pragma unroll
    for (int q = 0; q < 4; q++) {
        float a = v[2*q], b = v[2*q+1];
        __nv_bfloat162 hh = __floats2bfloat162_rn(a, b);
        float ra = a - __bfloat162float(__low2bfloat16(hh));
        float rb = b - __bfloat162float(__high2bfloat16(hh));
        __nv_bfloat162 ll = __floats2bfloat162_rn(ra, rb);
        hp[q] = bf2u(hh); lp[q] = bf2u(ll);
    }
    h = make_uint4(hp[0], hp[1], hp[2], hp[3]);
    l = make_uint4(lp[0], lp[1], lp[2], lp[3]);
}

// ---- prep kernel: W1/W2 -> swizzled bf16 hi/lo globals ----
__global__ void prep_weights(const float* __restrict__ W1,
                             const float* __restrict__ W2) {
    int t = blockIdx.x * blockDim.x + threadIdx.x;
    if (t < 32768) {                       // W1: [256k][128n]
        int k = t >> 7, n = t & 127;
        float v = W1[t];
        __nv_bfloat16 h = __float2bfloat16_rn(v);
        __nv_bfloat16 l = __float2bfloat16_rn(v - __bfloat162float(h));
        uint32_t off = (uint32_t)(k * 256 + ((((n >> 3) ^ (k & 7)) << 4) | ((n & 7) * 2)));
        *reinterpret_cast<__nv_bfloat16*>(g_w1hi + off) = h;
        *reinterpret_cast<__nv_bfloat16*>(g_w1lo + off) = l;
    } else if (t < 32768 + 128 * 144) {    // W2: [128k][144n], n>=136 pad zero
        int u = t - 32768;
        int k = u / 144, n = u - k * 144;
        float v = (n < TRIL) ? W2[k * TRIL + n] : 0.f;
        __nv_bfloat16 h = __float2bfloat16_rn(v);
        __nv_bfloat16 l = __float2bfloat16_rn(v - __bfloat162float(h));
        int c = n >> 3; if (c < 16) c ^= (k & 7);
        uint32_t off = (uint32_t)(k * 320 + (c << 4) + ((n & 7) * 2));
        *reinterpret_cast<__nv_bfloat16*>(g_w2hi + off) = h;
        *reinterpret_cast<__nv_bfloat16*>(g_w2lo + off) = l;
    }
}

// ---- stage 3: vectorized rho row (float4 stores; do NOT scalarize) ----
template <int I>
static __device__ __forceinline__ void rho_row(const float* __restrict__ vrow,
                                               float invtr,
                                               float* __restrict__ orow) {
    constexpr int TI = I * (I + 1) / 2;
    float Li[I + 1];
#pragma unroll
    for (int k = 0; k <= I; k++) Li[k] = vrow[TI + k];
    float res[16];
#pragma unroll
    for (int j = 0; j < 16; j++) {
        const int tj = j * (j + 1) / 2;
        const int len = (j < I) ? j : I;
        float dot = 0.f;
#pragma unroll
        for (int k = 0; k <= len; k++) dot = fmaf(Li[k], vrow[tj + k], dot);
        res[j] = dot * invtr;
    }
#pragma unroll
    for (int q = 0; q < 4; q++)
        *reinterpret_cast<float4*>(&orow[I * 16 + 4 * q]) =
            make_float4(res[4*q], res[4*q+1], res[4*q+2], res[4*q+3]);
}

__global__ void __launch_bounds__(THREADS)
density_mlp_hmma(const float* __restrict__ x,
                 const float* __restrict__ b1,
                 const float* __restrict__ b2,
                 float* __restrict__ out) {
    extern __shared__ char smem[];
    const uint32_t sb = smem_u32(smem);
    const int tid  = threadIdx.x;
    const int wid  = tid >> 5;
    const int lane = tid & 31;
    const int brow = blockIdx.x * ROWS;

    float* bias1 = reinterpret_cast<float*>(smem + OFF_B1);
    float* bias2 = reinterpret_cast<float*>(smem + OFF_B2);
    float* trc   = reinterpret_cast<float*>(smem + OFF_TR);

    bias1[tid] = b1[tid];
    if (tid < ROWS) trc[tid] = 0.f;
    for (int i = tid; i < TRIL; i += THREADS) bias2[i] = b2[i];

    const int m0  = (wid >> 1) * 32;      // warp row base {0,32}
    const int n0g = (wid & 1) * 64;       // warp col base (GEMM1)

    // ======================= GEMM1: 2 K-chunks of 128 =======================
    float acc[2][8][4];
#pragma unroll
    for (int mt = 0; mt < 2; mt++)
#pragma unroll
    for (int nt = 0; nt < 8; nt++)
#pragma unroll
    for (int q = 0; q < 4; q++) acc[mt][nt][q] = 0.f;

    for (int c = 0; c < 2; c++) {
        if (c) __syncthreads();           // warps done with previous chunk smem
        // W1 chunk: bare cp.async copies of pre-swizzled slabs
        {
            const unsigned char* sh = g_w1hi + c * 32768;
            const unsigned char* sl = g_w1lo + c * 32768;
#pragma unroll
            for (int i = 0; i < 16; i++) {
                int u = (tid + i * THREADS) * 16;    // 0..32752
                CP16(sb + W1HI + u, sh + u);
                CP16(sb + W1LO + u, sl + u);
            }
            CP_COMMIT();
        }
        // X chunk [64r x 128k] -> XHI/XLO (fp32 load + split)
#pragma unroll
        for (int i = 0; i < 8; i++) {
            int u = tid + i * THREADS;    // 0..1023
            int row = u >> 4, j = u & 15;
            const float* s = x + (size_t)(brow + row) * 256 + c * 128 + j * 8;
            float4 p = *reinterpret_cast<const float4*>(s);
            float4 q4 = *reinterpret_cast<const float4*>(s + 4);
            float v[8] = {p.x, p.y, p.z, p.w, q4.x, q4.y, q4.z, q4.w};
            uint4 h, l; split8(v, h, l);
            uint32_t off = swz256(row, j * 16);
            *reinterpret_cast<uint4*>(smem + XHI + off) = h;
            *reinterpret_cast<uint4*>(smem + XLO + off) = l;
        }
        CP_WAIT0();
        __syncthreads();

#pragma unroll
        for (int kt = 0; kt < 8; kt++) {
            uint32_t ah[2][4], al[2][4];
            ldsm_x4(lm256(sb + XHI, m0,      kt * 32, lane), ah[0]);
            ldsm_x4(lm256(sb + XHI, m0 + 16, kt * 32, lane), ah[1]);
            ldsm_x4(lm256(sb + XLO, m0,      kt * 32, lane), al[0]);
            ldsm_x4(lm256(sb + XLO, m0 + 16, kt * 32, lane), al[1]);
#pragma unroll
            for (int p = 0; p < 4; p++) {
                uint32_t th[4], tl[4];
                ldsm_x4t(lm256(sb + W1HI, kt * 16, (n0g + p * 16) * 2, lane), th);
                ldsm_x4t(lm256(sb + W1LO, kt * 16, (n0g + p * 16) * 2, lane), tl);
#pragma unroll
                for (int mt = 0; mt < 2; mt++) {
                    mma_bf16(acc[mt][2*p],   ah[mt], th);
                    mma_bf16(acc[mt][2*p],   ah[mt], tl);
                    mma_bf16(acc[mt][2*p],   al[mt], th);
                    mma_bf16(acc[mt][2*p+1], ah[mt], th + 2);
                    mma_bf16(acc[mt][2*p+1], ah[mt], tl + 2);
                    mma_bf16(acc[mt][2*p+1], al[mt], th + 2);
                }
            }
        }
    }
    __syncthreads();                      // GEMM1 done; X/W regions reusable

    // ============== epilogue 1: H = relu(C1+b1) -> HHI/HLO ==================
    // W2 chunk 0 copy first: cp.async overlaps with the epilogue math below
    {
#pragma unroll
        for (int i = 0; i < 10; i++) {
            int u = (tid + i * THREADS) * 16;        // 0..20464
            CP16(sb + W2HI + u, g_w2hi + u);
            CP16(sb + W2LO + u, g_w2lo + u);
        }
        CP_COMMIT();
    }
#pragma unroll
    for (int mt = 0; mt < 2; mt++)
#pragma unroll
    for (int nt = 0; nt < 8; nt++) {
        int col = n0g + nt * 8 + ((lane & 3) << 1);
        float ba = bias1[col], bb = bias1[col + 1];
        int r = m0 + mt * 16 + (lane >> 2);
#pragma unroll
        for (int half = 0; half < 2; half++) {
            float v0 = fmaxf(acc[mt][nt][2*half]     + ba, 0.f);
            float v1 = fmaxf(acc[mt][nt][2*half + 1] + bb, 0.f);
            __nv_bfloat162 hh = __floats2bfloat162_rn(v0, v1);
            float r0 = v0 - __bfloat162float(__low2bfloat16(hh));
            float r1 = v1 - __bfloat162float(__high2bfloat16(hh));
            __nv_bfloat162 ll = __floats2bfloat162_rn(r0, r1);
            uint32_t off = swz256(r + half * 8, col * 2);
            *reinterpret_cast<uint32_t*>(smem + HHI + off) = bf2u(hh);
            *reinterpret_cast<uint32_t*>(smem + HLO + off) = bf2u(ll);
        }
    }
    CP_WAIT0();
    __syncthreads();

    // ================= GEMM2: H @ W2, 2 K-chunks of 64 ======================
    const int n0g2 = (wid & 1) * 72;
    float acc2[2][9][4];
#pragma unroll
    for (int mt = 0; mt < 2; mt++)
#pragma unroll
    for (int nt = 0; nt < 9; nt++)
#pragma unroll
    for (int q = 0; q < 4; q++) acc2[mt][nt][q] = 0.f;

    for (int c2 = 0; c2 < 2; c2++) {
        if (c2) {
            __syncthreads();              // all warps done reading chunk 0
            {
#pragma unroll
                for (int i = 0; i < 10; i++) {
                    int u = (tid + i * THREADS) * 16;
                    CP16(sb + W2HI + u, g_w2hi + 20480 + u);
                    CP16(sb + W2LO + u, g_w2lo + 20480 + u);
                }
                CP_COMMIT();
            }
            CP_WAIT0();
            __syncthreads();
        }
#pragma unroll
        for (int kt = 0; kt < 4; kt++) {
            uint32_t ah[2][4], al[2][4];
            int bc0 = c2 * 128 + kt * 32;
            ldsm_x4(lm256(sb + HHI, m0,      bc0, lane), ah[0]);
            ldsm_x4(lm256(sb + HHI, m0 + 16, bc0, lane), ah[1]);
            ldsm_x4(lm256(sb + HLO, m0,      bc0, lane), al[0]);
            ldsm_x4(lm256(sb + HLO, m0 + 16, bc0, lane), al[1]);
#pragma unroll
            for (int p = 0; p < 4; p++) {
                uint32_t th[4], tl[4];
                ldsm_x4t(lm320(sb + W2HI, kt * 16, (n0g2 + p * 16) * 2, lane), th);
                ldsm_x4t(lm320(sb + W2LO, kt * 16, (n0g2 + p * 16) * 2, lane), tl);
#pragma unroll
                for (int mt = 0; mt < 2; mt++) {
                    mma_bf16(acc2[mt][2*p],   ah[mt], th);
                    mma_bf16(acc2[mt][2*p],   ah[mt], tl);
                    mma_bf16(acc2[mt][2*p],   al[mt], th);
                    mma_bf16(acc2[mt][2*p+1], ah[mt], th + 2);
                    mma_bf16(acc2[mt][2*p+1], ah[mt], tl + 2);
                    mma_bf16(acc2[mt][2*p+1], al[mt], th + 2);
                }
            }
            {
                uint32_t bh8[2], bl8[2];
                ldsm_x2t(lm320(sb + W2HI, kt * 16, (n0g2 + 64) * 2, lane), bh8);
                ldsm_x2t(lm320(sb + W2LO, kt * 16, (n0g2 + 64) * 2, lane), bl8);
#pragma unroll
                for (int mt = 0; mt < 2; mt++) {
                    mma_bf16(acc2[mt][8], ah[mt], bh8);
                    mma_bf16(acc2[mt][8], ah[mt], bl8);
                    mma_bf16(acc2[mt][8], al[mt], bh8);
                }
            }
        }
    }
    __syncthreads();                      // H/W2 regions reusable (Vs overlay)

    // ============ epilogue 2: V = C2+b2 -> Vs, trace ========================
    {
        float* Vs = reinterpret_cast<float*>(smem + OFF_VS);
        float part[2][2] = {{0.f, 0.f}, {0.f, 0.f}};
#pragma unroll
        for (int mt = 0; mt < 2; mt++)
#pragma unroll
        for (int nt = 0; nt < 9; nt++) {
            int col = n0g2 + nt * 8 + ((lane & 3) << 1);
            if (col < TRIL) {
                float ba = bias2[col];
                float bb = (col + 1 < TRIL) ? bias2[col + 1] : 0.f;
                int r = m0 + mt * 16 + (lane >> 2);
#pragma unroll
                for (int half = 0; half < 2; half++) {
                    float v0 = acc2[mt][nt][2*half] + ba;
                    Vs[(r + half*8) * VS_STRIDE + col] = v0;
                    part[mt][half] = fmaf(v0, v0, part[mt][half]);
                    if (col + 1 < TRIL) {
                        float v1 = acc2[mt][nt][2*half + 1] + bb;
                        Vs[(r + half*8) * VS_STRIDE + col + 1] = v1;
                        part[mt][half] = fmaf(v1, v1, part[mt][half]);
                    }
                }
            }
        }
        // reduce across the 4 lanes sharing a row, then one atomic
#pragma unroll
        for (int mt = 0; mt < 2; mt++)
#pragma unroll
        for (int half = 0; half < 2; half++) {
            float s = part[mt][half];
            s += __shfl_xor_sync(0xFFFFFFFF, s, 1);
            s += __shfl_xor_sync(0xFFFFFFFF, s, 2);
            if ((lane & 3) == 0)
                atomicAdd(&trc[m0 + mt * 16 + (lane >> 2) + half * 8], s);
        }
    }
    __syncthreads();

    // ===================== stage 3: rho = L L^T / trace =====================
    {
        const float* Vs = reinterpret_cast<const float*>(smem + OFF_VS);
        const int row = tid & (ROWS - 1);
        const int ib  = tid >> 6;             // 0: even i, 1: odd i
        const float* vrow = &Vs[row * VS_STRIDE];
        const float invtr = 1.0f / trc[row];
        float* orow = &out[(size_t)(brow + row) * 256];
        if (ib == 0) {
            rho_row<0>(vrow, invtr, orow);  rho_row<2>(vrow, invtr, orow);
            rho_row<4>(vrow, invtr, orow);  rho_row<6>(vrow, invtr, orow);
            rho_row<8>(vrow, invtr, orow);  rho_row<10>(vrow, invtr, orow);
            rho_row<12>(vrow, invtr, orow); rho_row<14>(vrow, invtr, orow);
        } else {
            rho_row<1>(vrow, invtr, orow);  rho_row<3>(vrow, invtr, orow);
            rho_row<5>(vrow, invtr, orow);  rho_row<7>(vrow, invtr, orow);
            rho_row<9>(vrow, invtr, orow);  rho_row<11>(vrow, invtr, orow);
            rho_row<13>(vrow, invtr, orow); rho_row<15>(vrow, invtr, orow);
        }
    }
}

extern "C" void kernel_launch(void* const* d_in, const int* in_sizes, int n_in,
                              void* d_out, int out_size) {
    const float* x  = (const float*)d_in[0];
    const float* W1 = (const float*)d_in[1];
    const float* b1 = (const float*)d_in[2];
    const float* W2 = (const float*)d_in[3];
    const float* b2 = (const float*)d_in[4];
    float* out = (float*)d_out;

    const int batch  = in_sizes[0] / 256;   // 131072
    const int blocks = batch / ROWS;        // 2048

    prep_weights<<<200, 256>>>(W1, W2);

    cudaFuncSetAttribute(density_mlp_hmma,
                         cudaFuncAttributeMaxDynamicSharedMemorySize, SMEM_BYTES);
    density_mlp_hmma<<<blocks, THREADS, SMEM_BYTES>>>(x, b1, b2, out);
}

// round 11
// speedup vs baseline: 2.1330x; 1.1261x over previous
#include <cuda_runtime.h>
#include <cuda_bf16.h>
#include <cstdint>

// ===========================================================================
// DensityMatrixMLP, fused bf16 split-precision mma.sync (HMMA), round 10.
// = round 9 with smem shrunk to 75776 B (W1 staged in four 64-k sub-chunks)
// so THREE 128-thread CTAs co-reside per SM:
//   regs: 3*128*170 = 65280 <= 65536   smem: 3*75776 = 227328 <= 233472
// 12 warps/SM (vs 8) to hide barrier/LDSM/epilogue latency.
// ===========================================================================

#define THREADS 128
#define ROWS    64
#define TRIL    136
#define VS_STRIDE 137

// ---- smem layout (bytes) ----
#define OFF_B1   0            // 128 f32
#define OFF_B2   512          // 136 f32
#define OFF_TR   1088         // 64 f32
#define OFF_A    2048         // 32 KB region (X / H, 64 rows x 128 k bf16)
#define XHI      (OFF_A)              // 64r x 256B
#define XLO      (OFF_A + 16384)
#define HHI      (OFF_A)              // overlay after GEMM1
#define HLO      (OFF_A + 16384)
#define OFF_W    (OFF_A + 32768)      // 40 KB weight region
#define W1HI     (OFF_W)              // 64k x 256B   (one 64-k sub-chunk)
#define W1LO     (OFF_W + 16384)
#define W2HI     (OFF_W)              // overlay: 64k x 320B per chunk
#define W2LO     (OFF_W + 20480)
#define OFF_VS   (OFF_A)              // Vs overlay: 64 x 137 f32 = 35072 B
#define SMEM_BYTES (OFF_W + 40960)    // 75776   (3 CTAs/SM: 227328)

// ---- pre-converted weights (swizzled, byte-identical to smem layouts) ----
__device__ __align__(16) unsigned char g_w1hi[256 * 256];   // [256k][256B]
__device__ __align__(16) unsigned char g_w1lo[256 * 256];
__device__ __align__(16) unsigned char g_w2hi[128 * 320];   // [128k][320B], n->144 pad
__device__ __align__(16) unsigned char g_w2lo[128 * 320];

static __device__ __forceinline__ uint32_t smem_u32(const void* p) {
    uint32_t a;
    asm("{ .reg .u64 t; cvta.to.shared.u64 t, %1; cvt.u32.u64 %0, t; }"
        : "=r"(a) : "l"(p));
    return a;
}

static __device__ __forceinline__ uint32_t swz256(int row, int bc) {
    return (uint32_t)(row * 256 + ((((bc >> 4) ^ (row & 7)) << 4) | (bc & 15)));
}
static __device__ __forceinline__ uint32_t swz320(int row, int bc) {
    int c = bc >> 4;
    if (c < 16) c ^= (row & 7);
    return (uint32_t)(row * 320 + (c << 4) + (bc & 15));
}
static __device__ __forceinline__ uint32_t lm256(uint32_t base, int r0, int bc0, int lane) {
    int row = r0 + (lane & 15), bc = bc0 + ((lane >> 4) << 4);
    return base + swz256(row, bc);
}
static __device__ __forceinline__ uint32_t lm320(uint32_t base, int r0, int bc0, int lane) {
    int row = r0 + (lane & 15), bc = bc0 + ((lane >> 4) << 4);
    return base + swz320(row, bc);
}

static __device__ __forceinline__ void ldsm_x4(uint32_t a, uint32_t r[4]) {
    asm volatile("ldmatrix.sync.aligned.m8n8.x4.shared.b16 {%0,%1,%2,%3}, [%4];"
                 : "=r"(r[0]), "=r"(r[1]), "=r"(r[2]), "=r"(r[3]) : "r"(a));
}
static __device__ __forceinline__ void ldsm_x4t(uint32_t a, uint32_t r[4]) {
    asm volatile("ldmatrix.sync.aligned.m8n8.x4.trans.shared.b16 {%0,%1,%2,%3}, [%4];"
                 : "=r"(r[0]), "=r"(r[1]), "=r"(r[2]), "=r"(r[3]) : "r"(a));
}
static __device__ __forceinline__ void ldsm_x2t(uint32_t a, uint32_t r[2]) {
    asm volatile("ldmatrix.sync.aligned.m8n8.x2.trans.shared.b16 {%0,%1}, [%2];"
                 : "=r"(r[0]), "=r"(r[1]) : "r"(a));
}
static __device__ __forceinline__ void mma_bf16(float d[4], const uint32_t a[4],
                                                const uint32_t* b) {
    asm volatile(
        "mma.sync.aligned.m16n8k16.row.col.f32.bf16.bf16.f32 "
        "{%0,%1,%2,%3}, {%4,%5,%6,%7}, {%8,%9}, {%0,%1,%2,%3};"
        : "+f"(d[0]), "+f"(d[1]), "+f"(d[2]), "+f"(d[3])
        : "r"(a[0]), "r"(a[1]), "r"(a[2]), "r"(a[3]), "r"(b[0]), "r"(b[1]));
}

#define CP16(dst, src) \
    asm volatile("cp.async.cg.shared.global [%0], [%1], 16;" :: "r"(dst), "l"(src))
#define CP_COMMIT() asm volatile("cp.async.commit_group;" ::: "memory")
#define CP_WAIT0()  asm volatile("cp.async.wait_group 0;" ::: "memory")

static __device__ __forceinline__ uint32_t bf2u(__nv_bfloat162 v) {
    return *reinterpret_cast<uint32_t*>(&v);
}
static __device__ __forceinline__ void split8(const float* v, uint4& h, uint4& l) {
    uint32_t hp[4], lp[4];
#pragma unroll
    for (int q = 0; q < 4; q++) {
        float a = v[2*q], b = v[2*q+1];
        __nv_bfloat162 hh = __floats2bfloat162_rn(a, b);
        float ra = a - __bfloat162float(__low2bfloat16(hh));
        float rb = b - __bfloat162float(__high2bfloat16(hh));
        __nv_bfloat162 ll = __floats2bfloat162_rn(ra, rb);
        hp[q] = bf2u(hh); lp[q] = bf2u(ll);
    }
    h = make_uint4(hp[0], hp[1], hp[2], hp[3]);
    l = make_uint4(lp[0], lp[1], lp[2], lp[3]);
}

// ---- prep kernel: W1/W2 -> swizzled bf16 hi/lo globals ----
__global__ void prep_weights(const float* __restrict__ W1,
                             const float* __restrict__ W2) {
    int t = blockIdx.x * blockDim.x + threadIdx.x;
    if (t < 32768) {                       // W1: [256k][128n]
        int k = t >> 7, n = t & 127;
        float v = W1[t];
        __nv_bfloat16 h = __float2bfloat16_rn(v);
        __nv_bfloat16 l = __float2bfloat16_rn(v - __bfloat162float(h));
        uint32_t off = (uint32_t)(k * 256 + ((((n >> 3) ^ (k & 7)) << 4) | ((n & 7) * 2)));
        *reinterpret_cast<__nv_bfloat16*>(g_w1hi + off) = h;
        *reinterpret_cast<__nv_bfloat16*>(g_w1lo + off) = l;
    } else if (t < 32768 + 128 * 144) {    // W2: [128k][144n], n>=136 pad zero
        int u = t - 32768;
        int k = u / 144, n = u - k * 144;
        float v = (n < TRIL) ? W2[k * TRIL + n] : 0.f;
        __nv_bfloat16 h = __float2bfloat16_rn(v);
        __nv_bfloat16 l = __float2bfloat16_rn(v - __bfloat162float(h));
        int c = n >> 3; if (c < 16) c ^= (k & 7);
        uint32_t off = (uint32_t)(k * 320 + (c << 4) + ((n & 7) * 2));
        *reinterpret_cast<__nv_bfloat16*>(g_w2hi + off) = h;
        *reinterpret_cast<__nv_bfloat16*>(g_w2lo + off) = l;
    }
}

// ---- stage 3: vectorized rho row (float4 stores; do NOT scalarize) ----
template <int I>
static __device__ __forceinline__ void rho_row(const float* __restrict__ vrow,
                                               float invtr,
                                               float* __restrict__ orow) {
    constexpr int TI = I * (I + 1) / 2;
    float Li[I + 1];
#pragma unroll
    for (int k = 0; k <= I; k++) Li[k] = vrow[TI + k];
    float res[16];
#pragma unroll
    for (int j = 0; j < 16; j++) {
        const int tj = j * (j + 1) / 2;
        const int len = (j < I) ? j : I;
        float dot = 0.f;
#pragma unroll
        for (int k = 0; k <= len; k++) dot = fmaf(Li[k], vrow[tj + k], dot);
        res[j] = dot * invtr;
    }
#pragma unroll
    for (int q = 0; q < 4; q++)
        *reinterpret_cast<float4*>(&orow[I * 16 + 4 * q]) =
            make_float4(res[4*q], res[4*q+1], res[4*q+2], res[4*q+3]);
}

__global__ void __launch_bounds__(THREADS, 3)
density_mlp_hmma(const float* __restrict__ x,
                 const float* __restrict__ b1,
                 const float* __restrict__ b2,
                 float* __restrict__ out) {
    extern __shared__ char smem[];
    const uint32_t sb = smem_u32(smem);
    const int tid  = threadIdx.x;
    const int wid  = tid >> 5;
    const int lane = tid & 31;
    const int brow = blockIdx.x * ROWS;

    float* bias1 = reinterpret_cast<float*>(smem + OFF_B1);
    float* bias2 = reinterpret_cast<float*>(smem + OFF_B2);
    float* trc   = reinterpret_cast<float*>(smem + OFF_TR);

    bias1[tid] = b1[tid];
    if (tid < ROWS) trc[tid] = 0.f;
    for (int i = tid; i < TRIL; i += THREADS) bias2[i] = b2[i];

    const int m0  = (wid >> 1) * 32;      // warp row base {0,32}
    const int n0g = (wid & 1) * 64;       // warp col base (GEMM1)

    // ============ GEMM1: 2 X-chunks of 128 k x 2 W1 sub-chunks of 64 k ======
    float acc[2][8][4];
#pragma unroll
    for (int mt = 0; mt < 2; mt++)
#pragma unroll
    for (int nt = 0; nt < 8; nt++)
#pragma unroll
    for (int q = 0; q < 4; q++) acc[mt][nt][q] = 0.f;

    for (int c = 0; c < 2; c++) {
        for (int w = 0; w < 2; w++) {
            const int cw = c * 2 + w;
            if (cw) __syncthreads();      // warps done with prev W1 (and X) smem
            // W1 sub-chunk cw: bare cp.async of pre-swizzled 16KB hi + lo slabs
            {
                const unsigned char* sh = g_w1hi + cw * 16384;
                const unsigned char* sl = g_w1lo + cw * 16384;
#pragma unroll
                for (int i = 0; i < 8; i++) {
                    int u = (tid + i * THREADS) * 16;    // 0..16368
                    CP16(sb + W1HI + u, sh + u);
                    CP16(sb + W1LO + u, sl + u);
                }
                CP_COMMIT();
            }
            // X chunk [64r x 128k] -> XHI/XLO, once per X chunk
            if (w == 0) {
#pragma unroll
                for (int i = 0; i < 8; i++) {
                    int u = tid + i * THREADS;    // 0..1023
                    int row = u >> 4, j = u & 15;
                    const float* s = x + (size_t)(brow + row) * 256 + c * 128 + j * 8;
                    float4 p = *reinterpret_cast<const float4*>(s);
                    float4 q4 = *reinterpret_cast<const float4*>(s + 4);
                    float v[8] = {p.x, p.y, p.z, p.w, q4.x, q4.y, q4.z, q4.w};
                    uint4 h, l; split8(v, h, l);
                    uint32_t off = swz256(row, j * 16);
                    *reinterpret_cast<uint4*>(smem + XHI + off) = h;
                    *reinterpret_cast<uint4*>(smem + XLO + off) = l;
                }
            }
            CP_WAIT0();
            __syncthreads();

#pragma unroll
            for (int kt = 0; kt < 4; kt++) {
                uint32_t ah[2][4], al[2][4];
                const int abc = w * 128 + kt * 32;       // byte col in X smem
                ldsm_x4(lm256(sb + XHI, m0,      abc, lane), ah[0]);
                ldsm_x4(lm256(sb + XHI, m0 + 16, abc, lane), ah[1]);
                ldsm_x4(lm256(sb + XLO, m0,      abc, lane), al[0]);
                ldsm_x4(lm256(sb + XLO, m0 + 16, abc, lane), al[1]);
#pragma unroll
                for (int p = 0; p < 4; p++) {
                    uint32_t th[4], tl[4];
                    ldsm_x4t(lm256(sb + W1HI, kt * 16, (n0g + p * 16) * 2, lane), th);
                    ldsm_x4t(lm256(sb + W1LO, kt * 16, (n0g + p * 16) * 2, lane), tl);
#pragma unroll
                    for (int mt = 0; mt < 2; mt++) {
                        mma_bf16(acc[mt][2*p],   ah[mt], th);
                        mma_bf16(acc[mt][2*p],   ah[mt], tl);
                        mma_bf16(acc[mt][2*p],   al[mt], th);
                        mma_bf16(acc[mt][2*p+1], ah[mt], th + 2);
                        mma_bf16(acc[mt][2*p+1], ah[mt], tl + 2);
                        mma_bf16(acc[mt][2*p+1], al[mt], th + 2);
                    }
                }
            }
        }
    }
    __syncthreads();                      // GEMM1 done; X/W regions reusable

    // ============== epilogue 1: H = relu(C1+b1) -> HHI/HLO ==================
    // W2 chunk 0 copy first: cp.async overlaps with the epilogue math below
    {
#pragma unroll
        for (int i = 0; i < 10; i++) {
            int u = (tid + i * THREADS) * 16;        // 0..20464
            CP16(sb + W2HI + u, g_w2hi + u);
            CP16(sb + W2LO + u, g_w2lo + u);
        }
        CP_COMMIT();
    }
#pragma unroll
    for (int mt = 0; mt < 2; mt++)
#pragma unroll
    for (int nt = 0; nt < 8; nt++) {
        int col = n0g + nt * 8 + ((lane & 3) << 1);
        float ba = bias1[col], bb = bias1[col + 1];
        int r = m0 + mt * 16 + (lane >> 2);
#pragma unroll
        for (int half = 0; half < 2; half++) {
            float v0 = fmaxf(acc[mt][nt][2*half]     + ba, 0.f);
            float v1 = fmaxf(acc[mt][nt][2*half + 1] + bb, 0.f);
            __nv_bfloat162 hh = __floats2bfloat162_rn(v0, v1);
            float r0 = v0 - __bfloat162float(__low2bfloat16(hh));
            float r1 = v1 - __bfloat162float(__high2bfloat16(hh));
            __nv_bfloat162 ll = __floats2bfloat162_rn(r0, r1);
            uint32_t off = swz256(r + half * 8, col * 2);
            *reinterpret_cast<uint32_t*>(smem + HHI + off) = bf2u(hh);
            *reinterpret_cast<uint32_t*>(smem + HLO + off) = bf2u(ll);
        }
    }
    CP_WAIT0();
    __syncthreads();

    // ================= GEMM2: H @ W2, 2 K-chunks of 64 ======================
    const int n0g2 = (wid & 1) * 72;
    float acc2[2][9][4];
#pragma unroll
    for (int mt = 0; mt < 2; mt++)
#pragma unroll
    for (int nt = 0; nt < 9; nt++)
#pragma unroll
    for (int q = 0; q < 4; q++) acc2[mt][nt][q] = 0.f;

    for (int c2 = 0; c2 < 2; c2++) {
        if (c2) {
            __syncthreads();              // all warps done reading chunk 0
            {
#pragma unroll
                for (int i = 0; i < 10; i++) {
                    int u = (tid + i * THREADS) * 16;
                    CP16(sb + W2HI + u, g_w2hi + 20480 + u);
                    CP16(sb + W2LO + u, g_w2lo + 20480 + u);
                }
                CP_COMMIT();
            }
            CP_WAIT0();
            __syncthreads();
        }
#pragma unroll
        for (int kt = 0; kt < 4; kt++) {
            uint32_t ah[2][4], al[2][4];
            int bc0 = c2 * 128 + kt * 32;
            ldsm_x4(lm256(sb + HHI, m0,      bc0, lane), ah[0]);
            ldsm_x4(lm256(sb + HHI, m0 + 16, bc0, lane), ah[1]);
            ldsm_x4(lm256(sb + HLO, m0,      bc0, lane), al[0]);
            ldsm_x4(lm256(sb + HLO, m0 + 16, bc0, lane), al[1]);
#pragma unroll
            for (int p = 0; p < 4; p++) {
                uint32_t th[4], tl[4];
                ldsm_x4t(lm320(sb + W2HI, kt * 16, (n0g2 + p * 16) * 2, lane), th);
                ldsm_x4t(lm320(sb + W2LO, kt * 16, (n0g2 + p * 16) * 2, lane), tl);
#pragma unroll
                for (int mt = 0; mt < 2; mt++) {
                    mma_bf16(acc2[mt][2*p],   ah[mt], th);
                    mma_bf16(acc2[mt][2*p],   ah[mt], tl);
                    mma_bf16(acc2[mt][2*p],   al[mt], th);
                    mma_bf16(acc2[mt][2*p+1], ah[mt], th + 2);
                    mma_bf16(acc2[mt][2*p+1], ah[mt], tl + 2);
                    mma_bf16(acc2[mt][2*p+1], al[mt], th + 2);
                }
            }
            {
                uint32_t bh8[2], bl8[2];
                ldsm_x2t(lm320(sb + W2HI, kt * 16, (n0g2 + 64) * 2, lane), bh8);
                ldsm_x2t(lm320(sb + W2LO, kt * 16, (n0g2 + 64) * 2, lane), bl8);
#pragma unroll
                for (int mt = 0; mt < 2; mt++) {
                    mma_bf16(acc2[mt][8], ah[mt], bh8);
                    mma_bf16(acc2[mt][8], ah[mt], bl8);
                    mma_bf16(acc2[mt][8], al[mt], bh8);
                }
            }
        }
    }
    __syncthreads();                      // H/W2 regions reusable (Vs overlay)

    // ============ epilogue 2: V = C2+b2 -> Vs, trace ========================
    {
        float* Vs = reinterpret_cast<float*>(smem + OFF_VS);
        float part[2][2] = {{0.f, 0.f}, {0.f, 0.f}};
#pragma unroll
        for (int mt = 0; mt < 2; mt++)
#pragma unroll
        for (int nt = 0; nt < 9; nt++) {
            int col = n0g2 + nt * 8 + ((lane & 3) << 1);
            if (col < TRIL) {
                float ba = bias2[col];
                float bb = (col + 1 < TRIL) ? bias2[col + 1] : 0.f;
                int r = m0 + mt * 16 + (lane >> 2);
#pragma unroll
                for (int half = 0; half < 2; half++) {
                    float v0 = acc2[mt][nt][2*half] + ba;
                    Vs[(r + half*8) * VS_STRIDE + col] = v0;
                    part[mt][half] = fmaf(v0, v0, part[mt][half]);
                    if (col + 1 < TRIL) {
                        float v1 = acc2[mt][nt][2*half + 1] + bb;
                        Vs[(r + half*8) * VS_STRIDE + col + 1] = v1;
                        part[mt][half] = fmaf(v1, v1, part[mt][half]);
                    }
                }
            }
        }
        // reduce across the 4 lanes sharing a row, then one atomic
#pragma unroll
        for (int mt = 0; mt < 2; mt++)
#pragma unroll
        for (int half = 0; half < 2; half++) {
            float s = part[mt][half];
            s += __shfl_xor_sync(0xFFFFFFFF, s, 1);
            s += __shfl_xor_sync(0xFFFFFFFF, s, 2);
            if ((lane & 3) == 0)
                atomicAdd(&trc[m0 + mt * 16 + (lane >> 2) + half * 8], s);
        }
    }
    __syncthreads();

    // ===================== stage 3: rho = L L^T / trace =====================
    {
        const float* Vs = reinterpret_cast<const float*>(smem + OFF_VS);
        const int row = tid & (ROWS - 1);
        const int ib  = tid >> 6;             // 0: even i, 1: odd i
        const float* vrow = &Vs[row * VS_STRIDE];
        const float invtr = 1.0f / trc[row];
        float* orow = &out[(size_t)(brow + row) * 256];
        if (ib == 0) {
            rho_row<0>(vrow, invtr, orow);  rho_row<2>(vrow, invtr, orow);
            rho_row<4>(vrow, invtr, orow);  rho_row<6>(vrow, invtr, orow);
            rho_row<8>(vrow, invtr, orow);  rho_row<10>(vrow, invtr, orow);
            rho_row<12>(vrow, invtr, orow); rho_row<14>(vrow, invtr, orow);
        } else {
            rho_row<1>(vrow, invtr, orow);  rho_row<3>(vrow, invtr, orow);
            rho_row<5>(vrow, invtr, orow);  rho_row<7>(vrow, invtr, orow);
            rho_row<9>(vrow, invtr, orow);  rho_row<11>(vrow, invtr, orow);
            rho_row<13>(vrow, invtr, orow); rho_row<15>(vrow, invtr, orow);
        }
    }
}

extern "C" void kernel_launch(void* const* d_in, const int* in_sizes, int n_in,
                              void* d_out, int out_size) {
    const float* x  = (const float*)d_in[0];
    const float* W1 = (const float*)d_in[1];
    const float* b1 = (const float*)d_in[2];
    const float* W2 = (const float*)d_in[3];
    const float* b2 = (const float*)d_in[4];
    float* out = (float*)d_out;

    const int batch  = in_sizes[0] / 256;   // 131072
    const int blocks = batch / ROWS;        // 2048

    prep_weights<<<200, 256>>>(W1, W2);

    cudaFuncSetAttribute(density_mlp_hmma,
                         cudaFuncAttributeMaxDynamicSharedMemorySize, SMEM_BYTES);
    density_mlp_hmma<<<blocks, THREADS, SMEM_BYTES>>>(x, b1, b2, out);
}

// round 12
// speedup vs baseline: 2.4323x; 1.1403x over previous
#include <cuda_runtime.h>
#include <cuda_fp16.h>
#include <cstdint>

// ===========================================================================
// DensityMatrixMLP, fused fp16 split-precision mma.sync (HMMA), round 11.
// = round 10 occupancy shape (128 thr, 64 rows, 3 CTAs/SM) with the split
// moved from bf16/3-term to fp16/2-term:
//   D = Ahi(f16)*B(f16) + Alo(f16)*B(f16);  B single-rounded fp16 (hi only).
// Products are exact in fp32; only error is B rounding (~2^-12 rel).
//  - 33% fewer MMAs, 50% less B-side smem + LDSM traffic
//  - W2 staged in ONE 40KB shot (no GEMM2 chunk split); W1 in 2 chunks
// ===========================================================================

#define THREADS 128
#define ROWS    64
#define TRIL    136
#define VS_STRIDE 137

// ---- smem layout (bytes) ----
#define OFF_B1   0            // 128 f32
#define OFF_B2   512          // 136 f32
#define OFF_TR   1088         // 64 f32
#define OFF_A    2048         // 32 KB region (X / H hi+lo, 64 r x 128 k f16)
#define XHI      (OFF_A)              // 64r x 256B
#define XLO      (OFF_A + 16384)
#define HHI      (OFF_A)              // overlay after GEMM1
#define HLO      (OFF_A + 16384)
#define OFF_W    (OFF_A + 32768)      // 40 KB weight region (hi only)
#define W1H      (OFF_W)              // 128k x 256B per chunk (32 KB)
#define W2H      (OFF_W)              // overlay: 128k x 320B = 40960 B
#define OFF_VS   (OFF_A)              // Vs overlay: 64 x 137 f32 = 35072 B
#define SMEM_BYTES (OFF_W + 40960)    // 75776   (3 CTAs/SM: 227328)

// ---- pre-converted weights (fp16, swizzled, byte-identical to smem) ----
__device__ __align__(16) unsigned char g_w1h[256 * 256];   // [256k][256B]
__device__ __align__(16) unsigned char g_w2h[128 * 320];   // [128k][320B], n->144 pad

static __device__ __forceinline__ uint32_t smem_u32(const void* p) {
    uint32_t a;
    asm("{ .reg .u64 t; cvta.to.shared.u64 t, %1; cvt.u32.u64 %0, t; }"
        : "=r"(a) : "l"(p));
    return a;
}

static __device__ __forceinline__ uint32_t swz256(int row, int bc) {
    return (uint32_t)(row * 256 + ((((bc >> 4) ^ (row & 7)) << 4) | (bc & 15)));
}
static __device__ __forceinline__ uint32_t swz320(int row, int bc) {
    int c = bc >> 4;
    if (c < 16) c ^= (row & 7);
    return (uint32_t)(row * 320 + (c << 4) + (bc & 15));
}
static __device__ __forceinline__ uint32_t lm256(uint32_t base, int r0, int bc0, int lane) {
    int row = r0 + (lane & 15), bc = bc0 + ((lane >> 4) << 4);
    return base + swz256(row, bc);
}
static __device__ __forceinline__ uint32_t lm320(uint32_t base, int r0, int bc0, int lane) {
    int row = r0 + (lane & 15), bc = bc0 + ((lane >> 4) << 4);
    return base + swz320(row, bc);
}

static __device__ __forceinline__ void ldsm_x4(uint32_t a, uint32_t r[4]) {
    asm volatile("ldmatrix.sync.aligned.m8n8.x4.shared.b16 {%0,%1,%2,%3}, [%4];"
                 : "=r"(r[0]), "=r"(r[1]), "=r"(r[2]), "=r"(r[3]) : "r"(a));
}
static __device__ __forceinline__ void ldsm_x4t(uint32_t a, uint32_t r[4]) {
    asm volatile("ldmatrix.sync.aligned.m8n8.x4.trans.shared.b16 {%0,%1,%2,%3}, [%4];"
                 : "=r"(r[0]), "=r"(r[1]), "=r"(r[2]), "=r"(r[3]) : "r"(a));
}
static __device__ __forceinline__ void ldsm_x2t(uint32_t a, uint32_t r[2]) {
    asm volatile("ldmatrix.sync.aligned.m8n8.x2.trans.shared.b16 {%0,%1}, [%2];"
                 : "=r"(r[0]), "=r"(r[1]) : "r"(a));
}
static __device__ __forceinline__ void mma_f16(float d[4], const uint32_t a[4],
                                               const uint32_t* b) {
    asm volatile(
        "mma.sync.aligned.m16n8k16.row.col.f32.f16.f16.f32 "
        "{%0,%1,%2,%3}, {%4,%5,%6,%7}, {%8,%9}, {%0,%1,%2,%3};"
        : "+f"(d[0]), "+f"(d[1]), "+f"(d[2]), "+f"(d[3])
        : "r"(a[0]), "r"(a[1]), "r"(a[2]), "r"(a[3]), "r"(b[0]), "r"(b[1]));
}

#define CP16(dst, src) \
    asm volatile("cp.async.cg.shared.global [%0], [%1], 16;" :: "r"(dst), "l"(src))
#define CP_COMMIT() asm volatile("cp.async.commit_group;" ::: "memory")
#define CP_WAIT0()  asm volatile("cp.async.wait_group 0;" ::: "memory")

static __device__ __forceinline__ uint32_t h2u(__half2 v) {
    return *reinterpret_cast<uint32_t*>(&v);
}
// split 8 fp32 -> 16B fp16 hi + 16B fp16 lo
static __device__ __forceinline__ void split8(const float* v, uint4& h, uint4& l) {
    uint32_t hp[4], lp[4];
#pragma unroll
    for (int q = 0; q < 4; q++) {
        float a = v[2*q], b = v[2*q+1];
        __half2 hh = __floats2half2_rn(a, b);
        float ra = a - __half2float(__low2half(hh));
        float rb = b - __half2float(__high2half(hh));
        __half2 ll = __floats2half2_rn(ra, rb);
        hp[q] = h2u(hh); lp[q] = h2u(ll);
    }
    h = make_uint4(hp[0], hp[1], hp[2], hp[3]);
    l = make_uint4(lp[0], lp[1], lp[2], lp[3]);
}

// ---- prep kernel: W1/W2 -> swizzled fp16 globals (hi only) ----
__global__ void prep_weights(const float* __restrict__ W1,
                             const float* __restrict__ W2) {
    int t = blockIdx.x * blockDim.x + threadIdx.x;
    if (t < 32768) {                       // W1: [256k][128n]
        int k = t >> 7, n = t & 127;
        uint32_t off = (uint32_t)(k * 256 + ((((n >> 3) ^ (k & 7)) << 4) | ((n & 7) * 2)));
        *reinterpret_cast<__half*>(g_w1h + off) = __float2half_rn(W1[t]);
    } else if (t < 32768 + 128 * 144) {    // W2: [128k][144n], n>=136 pad zero
        int u = t - 32768;
        int k = u / 144, n = u - k * 144;
        float v = (n < TRIL) ? W2[k * TRIL + n] : 0.f;
        int c = n >> 3; if (c < 16) c ^= (k & 7);
        uint32_t off = (uint32_t)(k * 320 + (c << 4) + ((n & 7) * 2));
        *reinterpret_cast<__half*>(g_w2h + off) = __float2half_rn(v);
    }
}

// ---- stage 3: vectorized rho row (float4 stores; do NOT scalarize) ----
template <int I>
static __device__ __forceinline__ void rho_row(const float* __restrict__ vrow,
                                               float invtr,
                                               float* __restrict__ orow) {
    constexpr int TI = I * (I + 1) / 2;
    float Li[I + 1];
#pragma unroll
    for (int k = 0; k <= I; k++) Li[k] = vrow[TI + k];
    float res[16];
#pragma unroll
    for (int j = 0; j < 16; j++) {
        const int tj = j * (j + 1) / 2;
        const int len = (j < I) ? j : I;
        float dot = 0.f;
#pragma unroll
        for (int k = 0; k <= len; k++) dot = fmaf(Li[k], vrow[tj + k], dot);
        res[j] = dot * invtr;
    }
#pragma unroll
    for (int q = 0; q < 4; q++)
        *reinterpret_cast<float4*>(&orow[I * 16 + 4 * q]) =
            make_float4(res[4*q], res[4*q+1], res[4*q+2], res[4*q+3]);
}

__global__ void __launch_bounds__(THREADS, 3)
density_mlp_hmma(const float* __restrict__ x,
                 const float* __restrict__ b1,
                 const float* __restrict__ b2,
                 float* __restrict__ out) {
    extern __shared__ char smem[];
    const uint32_t sb = smem_u32(smem);
    const int tid  = threadIdx.x;
    const int wid  = tid >> 5;
    const int lane = tid & 31;
    const int brow = blockIdx.x * ROWS;

    float* bias1 = reinterpret_cast<float*>(smem + OFF_B1);
    float* bias2 = reinterpret_cast<float*>(smem + OFF_B2);
    float* trc   = reinterpret_cast<float*>(smem + OFF_TR);

    bias1[tid] = b1[tid];
    if (tid < ROWS) trc[tid] = 0.f;
    for (int i = tid; i < TRIL; i += THREADS) bias2[i] = b2[i];

    const int m0  = (wid >> 1) * 32;      // warp row base {0,32}
    const int n0g = (wid & 1) * 64;       // warp col base (GEMM1)

    // ======================= GEMM1: 2 K-chunks of 128 =======================
    float acc[2][8][4];
#pragma unroll
    for (int mt = 0; mt < 2; mt++)
#pragma unroll
    for (int nt = 0; nt < 8; nt++)
#pragma unroll
    for (int q = 0; q < 4; q++) acc[mt][nt][q] = 0.f;

    for (int c = 0; c < 2; c++) {
        if (c) __syncthreads();           // warps done with previous chunk smem
        // W1 chunk (hi only, 32KB): bare cp.async of pre-swizzled slab
        {
            const unsigned char* sh = g_w1h + c * 32768;
#pragma unroll
            for (int i = 0; i < 16; i++) {
                int u = (tid + i * THREADS) * 16;    // 0..32752
                CP16(sb + W1H + u, sh + u);
            }
            CP_COMMIT();
        }
        // X chunk [64r x 128k] -> XHI/XLO (fp32 load + fp16 split)
#pragma unroll
        for (int i = 0; i < 8; i++) {
            int u = tid + i * THREADS;    // 0..1023
            int row = u >> 4, j = u & 15;
            const float* s = x + (size_t)(brow + row) * 256 + c * 128 + j * 8;
            float4 p = *reinterpret_cast<const float4*>(s);
            float4 q4 = *reinterpret_cast<const float4*>(s + 4);
            float v[8] = {p.x, p.y, p.z, p.w, q4.x, q4.y, q4.z, q4.w};
            uint4 h, l; split8(v, h, l);
            uint32_t off = swz256(row, j * 16);
            *reinterpret_cast<uint4*>(smem + XHI + off) = h;
            *reinterpret_cast<uint4*>(smem + XLO + off) = l;
        }
        CP_WAIT0();
        __syncthreads();

#pragma unroll
        for (int kt = 0; kt < 8; kt++) {
            uint32_t ah[2][4], al[2][4];
            ldsm_x4(lm256(sb + XHI, m0,      kt * 32, lane), ah[0]);
            ldsm_x4(lm256(sb + XHI, m0 + 16, kt * 32, lane), ah[1]);
            ldsm_x4(lm256(sb + XLO, m0,      kt * 32, lane), al[0]);
            ldsm_x4(lm256(sb + XLO, m0 + 16, kt * 32, lane), al[1]);
#pragma unroll
            for (int p = 0; p < 4; p++) {
                uint32_t th[4];
                ldsm_x4t(lm256(sb + W1H, kt * 16, (n0g + p * 16) * 2, lane), th);
#pragma unroll
                for (int mt = 0; mt < 2; mt++) {
                    mma_f16(acc[mt][2*p],   ah[mt], th);
                    mma_f16(acc[mt][2*p],   al[mt], th);
                    mma_f16(acc[mt][2*p+1], ah[mt], th + 2);
                    mma_f16(acc[mt][2*p+1], al[mt], th + 2);
                }
            }
        }
    }
    __syncthreads();                      // GEMM1 done; X/W regions reusable

    // ============== epilogue 1: H = relu(C1+b1) -> HHI/HLO ==================
    // W2 (hi only, 40KB, ONE shot): cp.async overlaps with epilogue math
    {
#pragma unroll
        for (int i = 0; i < 20; i++) {
            int u = (tid + i * THREADS) * 16;        // 0..40944
            CP16(sb + W2H + u, g_w2h + u);
        }
        CP_COMMIT();
    }
#pragma unroll
    for (int mt = 0; mt < 2; mt++)
#pragma unroll
    for (int nt = 0; nt < 8; nt++) {
        int col = n0g + nt * 8 + ((lane & 3) << 1);
        float ba = bias1[col], bb = bias1[col + 1];
        int r = m0 + mt * 16 + (lane >> 2);
#pragma unroll
        for (int half = 0; half < 2; half++) {
            float v0 = fmaxf(acc[mt][nt][2*half]     + ba, 0.f);
            float v1 = fmaxf(acc[mt][nt][2*half + 1] + bb, 0.f);
            __half2 hh = __floats2half2_rn(v0, v1);
            float r0 = v0 - __half2float(__low2half(hh));
            float r1 = v1 - __half2float(__high2half(hh));
            __half2 ll = __floats2half2_rn(r0, r1);
            uint32_t off = swz256(r + half * 8, col * 2);
            *reinterpret_cast<uint32_t*>(smem + HHI + off) = h2u(hh);
            *reinterpret_cast<uint32_t*>(smem + HLO + off) = h2u(ll);
        }
    }
    CP_WAIT0();
    __syncthreads();

    // ================= GEMM2: H @ W2, single pass over K=128 ================
    const int n0g2 = (wid & 1) * 72;
    float acc2[2][9][4];
#pragma unroll
    for (int mt = 0; mt < 2; mt++)
#pragma unroll
    for (int nt = 0; nt < 9; nt++)
#pragma unroll
    for (int q = 0; q < 4; q++) acc2[mt][nt][q] = 0.f;

#pragma unroll
    for (int kt = 0; kt < 8; kt++) {
        uint32_t ah[2][4], al[2][4];
        ldsm_x4(lm256(sb + HHI, m0,      kt * 32, lane), ah[0]);
        ldsm_x4(lm256(sb + HHI, m0 + 16, kt * 32, lane), ah[1]);
        ldsm_x4(lm256(sb + HLO, m0,      kt * 32, lane), al[0]);
        ldsm_x4(lm256(sb + HLO, m0 + 16, kt * 32, lane), al[1]);
#pragma unroll
        for (int p = 0; p < 4; p++) {
            uint32_t th[4];
            ldsm_x4t(lm320(sb + W2H, kt * 16, (n0g2 + p * 16) * 2, lane), th);
#pragma unroll
            for (int mt = 0; mt < 2; mt++) {
                mma_f16(acc2[mt][2*p],   ah[mt], th);
                mma_f16(acc2[mt][2*p],   al[mt], th);
                mma_f16(acc2[mt][2*p+1], ah[mt], th + 2);
                mma_f16(acc2[mt][2*p+1], al[mt], th + 2);
            }
        }
        {
            uint32_t th8[2];
            ldsm_x2t(lm320(sb + W2H, kt * 16, (n0g2 + 64) * 2, lane), th8);
#pragma unroll
            for (int mt = 0; mt < 2; mt++) {
                mma_f16(acc2[mt][8], ah[mt], th8);
                mma_f16(acc2[mt][8], al[mt], th8);
            }
        }
    }
    __syncthreads();                      // H/W2 regions reusable (Vs overlay)

    // ============ epilogue 2: V = C2+b2 -> Vs, trace ========================
    {
        float* Vs = reinterpret_cast<float*>(smem + OFF_VS);
        float part[2][2] = {{0.f, 0.f}, {0.f, 0.f}};
#pragma unroll
        for (int mt = 0; mt < 2; mt++)
#pragma unroll
        for (int nt = 0; nt < 9; nt++) {
            int col = n0g2 + nt * 8 + ((lane & 3) << 1);
            if (col < TRIL) {
                float ba = bias2[col];
                float bb = (col + 1 < TRIL) ? bias2[col + 1] : 0.f;
                int r = m0 + mt * 16 + (lane >> 2);
#pragma unroll
                for (int half = 0; half < 2; half++) {
                    float v0 = acc2[mt][nt][2*half] + ba;
                    Vs[(r + half*8) * VS_STRIDE + col] = v0;
                    part[mt][half] = fmaf(v0, v0, part[mt][half]);
                    if (col + 1 < TRIL) {
                        float v1 = acc2[mt][nt][2*half + 1] + bb;
                        Vs[(r + half*8) * VS_STRIDE + col + 1] = v1;
                        part[mt][half] = fmaf(v1, v1, part[mt][half]);
                    }
                }
            }
        }
        // reduce across the 4 lanes sharing a row, then one atomic
#pragma unroll
        for (int mt = 0; mt < 2; mt++)
#pragma unroll
        for (int half = 0; half < 2; half++) {
            float s = part[mt][half];
            s += __shfl_xor_sync(0xFFFFFFFF, s, 1);
            s += __shfl_xor_sync(0xFFFFFFFF, s, 2);
            if ((lane & 3) == 0)
                atomicAdd(&trc[m0 + mt * 16 + (lane >> 2) + half * 8], s);
        }
    }
    __syncthreads();

    // ===================== stage 3: rho = L L^T / trace =====================
    {
        const float* Vs = reinterpret_cast<const float*>(smem + OFF_VS);
        const int row = tid & (ROWS - 1);
        const int ib  = tid >> 6;             // 0: even i, 1: odd i
        const float* vrow = &Vs[row * VS_STRIDE];
        const float invtr = 1.0f / trc[row];
        float* orow = &out[(size_t)(brow + row) * 256];
        if (ib == 0) {
            rho_row<0>(vrow, invtr, orow);  rho_row<2>(vrow, invtr, orow);
            rho_row<4>(vrow, invtr, orow);  rho_row<6>(vrow, invtr, orow);
            rho_row<8>(vrow, invtr, orow);  rho_row<10>(vrow, invtr, orow);
            rho_row<12>(vrow, invtr, orow); rho_row<14>(vrow, invtr, orow);
        } else {
            rho_row<1>(vrow, invtr, orow);  rho_row<3>(vrow, invtr, orow);
            rho_row<5>(vrow, invtr, orow);  rho_row<7>(vrow, invtr, orow);
            rho_row<9>(vrow, invtr, orow);  rho_row<11>(vrow, invtr, orow);
            rho_row<13>(vrow, invtr, orow); rho_row<15>(vrow, invtr, orow);
        }
    }
}

extern "C" void kernel_launch(void* const* d_in, const int* in_sizes, int n_in,
                              void* d_out, int out_size) {
    const float* x  = (const float*)d_in[0];
    const float* W1 = (const float*)d_in[1];
    const float* b1 = (const float*)d_in[2];
    const float* W2 = (const float*)d_in[3];
    const float* b2 = (const float*)d_in[4];
    float* out = (float*)d_out;

    const int batch  = in_sizes[0] / 256;   // 131072
    const int blocks = batch / ROWS;        // 2048

    prep_weights<<<200, 256>>>(W1, W2);

    cudaFuncSetAttribute(density_mlp_hmma,
                         cudaFuncAttributeMaxDynamicSharedMemorySize, SMEM_BYTES);
    density_mlp_hmma<<<blocks, THREADS, SMEM_BYTES>>>(x, b1, b2, out);
}

// round 14
// speedup vs baseline: 2.9556x; 1.2152x over previous
#include <cuda_runtime.h>
#include <cuda_fp16.h>
#include <cstdint>

// ===========================================================================
// DensityMatrixMLP, fused PLAIN fp16 mma.sync (HMMA), round 12.
// = round 11 with both A-side lo terms dropped: straight fp16 GEMMs, fp32
// accum. Calibrated error model: ~4.5-5.5e-4 rel (gate 1e-3).
//  - mma count halved (800 -> 400 per warp)
//  - A-side LDSM + conversion work halved; smem 59.4 KB (3 CTAs/SM)
// Fallback if rel_err > 1e-3: revert to round-11 (129.8 us, 2.98e-4).
// ===========================================================================

#define THREADS 128
#define ROWS    64
#define TRIL    136
#define VS_STRIDE 137

// ---- smem layout (bytes) ----
#define OFF_B1   0            // 128 f32
#define OFF_B2   512          // 136 f32
#define OFF_TR   1088         // 64 f32
#define OFF_A    2048         // 16 KB region (X / H fp16, 64 r x 128 k)
#define XH       (OFF_A)              // 64r x 256B
#define HH       (OFF_A)              // overlay after GEMM1
#define OFF_W    (OFF_A + 16384)      // 40 KB weight region
#define W1H      (OFF_W)              // 128k x 256B per chunk (32 KB used)
#define W2H      (OFF_W)              // overlay: 128k x 320B = 40960 B
#define OFF_VS   (OFF_A)              // Vs overlay: 64 x 137 f32 = 35072 B
                                      // (spans X+W regions, both dead then)
#define SMEM_BYTES (OFF_W + 40960)    // 59392   (3 CTAs/SM: 178176)

// ---- pre-converted weights (fp16, swizzled, byte-identical to smem) ----
__device__ __align__(16) unsigned char g_w1h[256 * 256];   // [256k][256B]
__device__ __align__(16) unsigned char g_w2h[128 * 320];   // [128k][320B], n->144 pad

static __device__ __forceinline__ uint32_t smem_u32(const void* p) {
    uint32_t a;
    asm("{ .reg .u64 t; cvta.to.shared.u64 t, %1; cvt.u32.u64 %0, t; }"
        : "=r"(a) : "l"(p));
    return a;
}

static __device__ __forceinline__ uint32_t swz256(int row, int bc) {
    return (uint32_t)(row * 256 + ((((bc >> 4) ^ (row & 7)) << 4) | (bc & 15)));
}
static __device__ __forceinline__ uint32_t swz320(int row, int bc) {
    int c = bc >> 4;
    if (c < 16) c ^= (row & 7);
    return (uint32_t)(row * 320 + (c << 4) + (bc & 15));
}
static __device__ __forceinline__ uint32_t lm256(uint32_t base, int r0, int bc0, int lane) {
    int row = r0 + (lane & 15), bc = bc0 + ((lane >> 4) << 4);
    return base + swz256(row, bc);
}
static __device__ __forceinline__ uint32_t lm320(uint32_t base, int r0, int bc0, int lane) {
    int row = r0 + (lane & 15), bc = bc0 + ((lane >> 4) << 4);
    return base + swz320(row, bc);
}

static __device__ __forceinline__ void ldsm_x4(uint32_t a, uint32_t r[4]) {
    asm volatile("ldmatrix.sync.aligned.m8n8.x4.shared.b16 {%0,%1,%2,%3}, [%4];"
                 : "=r"(r[0]), "=r"(r[1]), "=r"(r[2]), "=r"(r[3]) : "r"(a));
}
static __device__ __forceinline__ void ldsm_x4t(uint32_t a, uint32_t r[4]) {
    asm volatile("ldmatrix.sync.aligned.m8n8.x4.trans.shared.b16 {%0,%1,%2,%3}, [%4];"
                 : "=r"(r[0]), "=r"(r[1]), "=r"(r[2]), "=r"(r[3]) : "r"(a));
}
static __device__ __forceinline__ void ldsm_x2t(uint32_t a, uint32_t r[2]) {
    asm volatile("ldmatrix.sync.aligned.m8n8.x2.trans.shared.b16 {%0,%1}, [%2];"
                 : "=r"(r[0]), "=r"(r[1]) : "r"(a));
}
static __device__ __forceinline__ void mma_f16(float d[4], const uint32_t a[4],
                                               const uint32_t* b) {
    asm volatile(
        "mma.sync.aligned.m16n8k16.row.col.f32.f16.f16.f32 "
        "{%0,%1,%2,%3}, {%4,%5,%6,%7}, {%8,%9}, {%0,%1,%2,%3};"
        : "+f"(d[0]), "+f"(d[1]), "+f"(d[2]), "+f"(d[3])
        : "r"(a[0]), "r"(a[1]), "r"(a[2]), "r"(a[3]), "r"(b[0]), "r"(b[1]));
}

#define CP16(dst, src) \
    asm volatile("cp.async.cg.shared.global [%0], [%1], 16;" :: "r"(dst), "l"(src))
#define CP_COMMIT() asm volatile("cp.async.commit_group;" ::: "memory")
#define CP_WAIT0()  asm volatile("cp.async.wait_group 0;" ::: "memory")

static __device__ __forceinline__ uint32_t h2u(__half2 v) {
    return *reinterpret_cast<uint32_t*>(&v);
}
// convert 8 fp32 -> 16B fp16 (single-rounded)
static __device__ __forceinline__ uint4 cvt8(const float* v) {
    uint32_t p[4];
#pragma unroll
    for (int q = 0; q < 4; q++)
        p[q] = h2u(__floats2half2_rn(v[2*q], v[2*q+1]));
    return make_uint4(p[0], p[1], p[2], p[3]);
}

// ---- prep kernel: W1/W2 -> swizzled fp16 globals ----
__global__ void prep_weights(const float* __restrict__ W1,
                             const float* __restrict__ W2) {
    int t = blockIdx.x * blockDim.x + threadIdx.x;
    if (t < 32768) {                       // W1: [256k][128n]
        int k = t >> 7, n = t & 127;
        uint32_t off = (uint32_t)(k * 256 + ((((n >> 3) ^ (k & 7)) << 4) | ((n & 7) * 2)));
        *reinterpret_cast<__half*>(g_w1h + off) = __float2half_rn(W1[t]);
    } else if (t < 32768 + 128 * 144) {    // W2: [128k][144n], n>=136 pad zero
        int u = t - 32768;
        int k = u / 144, n = u - k * 144;
        float v = (n < TRIL) ? W2[k * TRIL + n] : 0.f;
        int c = n >> 3; if (c < 16) c ^= (k & 7);
        uint32_t off = (uint32_t)(k * 320 + (c << 4) + ((n & 7) * 2));
        *reinterpret_cast<__half*>(g_w2h + off) = __float2half_rn(v);
    }
}

// ---- stage 3: vectorized rho row (float4 stores; do NOT scalarize) ----
template <int I>
static __device__ __forceinline__ void rho_row(const float* __restrict__ vrow,
                                               float invtr,
                                               float* __restrict__ orow) {
    constexpr int TI = I * (I + 1) / 2;
    float Li[I + 1];
#pragma unroll
    for (int k = 0; k <= I; k++) Li[k] = vrow[TI + k];
    float res[16];
#pragma unroll
    for (int j = 0; j < 16; j++) {
        const int tj = j * (j + 1) / 2;
        const int len = (j < I) ? j : I;
        float dot = 0.f;
#pragma unroll
        for (int k = 0; k <= len; k++) dot = fmaf(Li[k], vrow[tj + k], dot);
        res[j] = dot * invtr;
    }
#pragma unroll
    for (int q = 0; q < 4; q++)
        *reinterpret_cast<float4*>(&orow[I * 16 + 4 * q]) =
            make_float4(res[4*q], res[4*q+1], res[4*q+2], res[4*q+3]);
}

__global__ void __launch_bounds__(THREADS, 3)
density_mlp_hmma(const float* __restrict__ x,
                 const float* __restrict__ b1,
                 const float* __restrict__ b2,
                 float* __restrict__ out) {
    extern __shared__ char smem[];
    const uint32_t sb = smem_u32(smem);
    const int tid  = threadIdx.x;
    const int wid  = tid >> 5;
    const int lane = tid & 31;
    const int brow = blockIdx.x * ROWS;

    float* bias1 = reinterpret_cast<float*>(smem + OFF_B1);
    float* bias2 = reinterpret_cast<float*>(smem + OFF_B2);
    float* trc   = reinterpret_cast<float*>(smem + OFF_TR);

    bias1[tid] = b1[tid];
    if (tid < ROWS) trc[tid] = 0.f;
    for (int i = tid; i < TRIL; i += THREADS) bias2[i] = b2[i];

    const int m0  = (wid >> 1) * 32;      // warp row base {0,32}
    const int n0g = (wid & 1) * 64;       // warp col base (GEMM1)

    // ======================= GEMM1: 2 K-chunks of 128 =======================
    float acc[2][8][4];
#pragma unroll
    for (int mt = 0; mt < 2; mt++)
#pragma unroll
    for (int nt = 0; nt < 8; nt++)
#pragma unroll
    for (int q = 0; q < 4; q++) acc[mt][nt][q] = 0.f;

    for (int c = 0; c < 2; c++) {
        if (c) __syncthreads();           // warps done with previous chunk smem
        // W1 chunk (32KB): bare cp.async of pre-swizzled slab
        {
            const unsigned char* sh = g_w1h + c * 32768;
#pragma unroll
            for (int i = 0; i < 16; i++) {
                int u = (tid + i * THREADS) * 16;    // 0..32752
                CP16(sb + W1H + u, sh + u);
            }
            CP_COMMIT();
        }
        // X chunk [64r x 128k] -> XH (fp32 load + fp16 convert)
#pragma unroll
        for (int i = 0; i < 8; i++) {
            int u = tid + i * THREADS;    // 0..1023
            int row = u >> 4, j = u & 15;
            const float* s = x + (size_t)(brow + row) * 256 + c * 128 + j * 8;
            float4 p = *reinterpret_cast<const float4*>(s);
            float4 q4 = *reinterpret_cast<const float4*>(s + 4);
            float v[8] = {p.x, p.y, p.z, p.w, q4.x, q4.y, q4.z, q4.w};
            *reinterpret_cast<uint4*>(smem + XH + swz256(row, j * 16)) = cvt8(v);
        }
        CP_WAIT0();
        __syncthreads();

#pragma unroll
        for (int kt = 0; kt < 8; kt++) {
            uint32_t ah[2][4];
            ldsm_x4(lm256(sb + XH, m0,      kt * 32, lane), ah[0]);
            ldsm_x4(lm256(sb + XH, m0 + 16, kt * 32, lane), ah[1]);
#pragma unroll
            for (int p = 0; p < 4; p++) {
                uint32_t th[4];
                ldsm_x4t(lm256(sb + W1H, kt * 16, (n0g + p * 16) * 2, lane), th);
#pragma unroll
                for (int mt = 0; mt < 2; mt++) {
                    mma_f16(acc[mt][2*p],   ah[mt], th);
                    mma_f16(acc[mt][2*p+1], ah[mt], th + 2);
                }
            }
        }
    }
    __syncthreads();                      // GEMM1 done; X/W regions reusable

    // ============== epilogue 1: H = relu(C1+b1) -> HH (fp16) ================
    // W2 (40KB, ONE shot): cp.async overlaps with epilogue math
    {
#pragma unroll
        for (int i = 0; i < 20; i++) {
            int u = (tid + i * THREADS) * 16;        // 0..40944
            CP16(sb + W2H + u, g_w2h + u);
        }
        CP_COMMIT();
    }
#pragma unroll
    for (int mt = 0; mt < 2; mt++)
#pragma unroll
    for (int nt = 0; nt < 8; nt++) {
        int col = n0g + nt * 8 + ((lane & 3) << 1);
        float ba = bias1[col], bb = bias1[col + 1];
        int r = m0 + mt * 16 + (lane >> 2);
#pragma unroll
        for (int half = 0; half < 2; half++) {
            float v0 = fmaxf(acc[mt][nt][2*half]     + ba, 0.f);
            float v1 = fmaxf(acc[mt][nt][2*half + 1] + bb, 0.f);
            uint32_t off = swz256(r + half * 8, col * 2);
            *reinterpret_cast<uint32_t*>(smem + HH + off) =
                h2u(__floats2half2_rn(v0, v1));
        }
    }
    CP_WAIT0();
    __syncthreads();

    // ================= GEMM2: H @ W2, single pass over K=128 ================
    const int n0g2 = (wid & 1) * 72;
    float acc2[2][9][4];
#pragma unroll
    for (int mt = 0; mt < 2; mt++)
#pragma unroll
    for (int nt = 0; nt < 9; nt++)
#pragma unroll
    for (int q = 0; q < 4; q++) acc2[mt][nt][q] = 0.f;

#pragma unroll
    for (int kt = 0; kt < 8; kt++) {
        uint32_t ah[2][4];
        ldsm_x4(lm256(sb + HH, m0,      kt * 32, lane), ah[0]);
        ldsm_x4(lm256(sb + HH, m0 + 16, kt * 32, lane), ah[1]);
#pragma unroll
        for (int p = 0; p < 4; p++) {
            uint32_t th[4];
            ldsm_x4t(lm320(sb + W2H, kt * 16, (n0g2 + p * 16) * 2, lane), th);
#pragma unroll
            for (int mt = 0; mt < 2; mt++) {
                mma_f16(acc2[mt][2*p],   ah[mt], th);
                mma_f16(acc2[mt][2*p+1], ah[mt], th + 2);
            }
        }
        {
            uint32_t th8[2];
            ldsm_x2t(lm320(sb + W2H, kt * 16, (n0g2 + 64) * 2, lane), th8);
#pragma unroll
            for (int mt = 0; mt < 2; mt++)
                mma_f16(acc2[mt][8], ah[mt], th8);
        }
    }
    __syncthreads();                      // H/W2 regions reusable (Vs overlay)

    // ============ epilogue 2: V = C2+b2 -> Vs, trace ========================
    {
        float* Vs = reinterpret_cast<float*>(smem + OFF_VS);
        float part[2][2] = {{0.f, 0.f}, {0.f, 0.f}};
#pragma unroll
        for (int mt = 0; mt < 2; mt++)
#pragma unroll
        for (int nt = 0; nt < 9; nt++) {
            int col = n0g2 + nt * 8 + ((lane & 3) << 1);
            if (col < TRIL) {
                float ba = bias2[col];
                float bb = (col + 1 < TRIL) ? bias2[col + 1] : 0.f;
                int r = m0 + mt * 16 + (lane >> 2);
#pragma unroll
                for (int half = 0; half < 2; half++) {
                    float v0 = acc2[mt][nt][2*half] + ba;
                    Vs[(r + half*8) * VS_STRIDE + col] = v0;
                    part[mt][half] = fmaf(v0, v0, part[mt][half]);
                    if (col + 1 < TRIL) {
                        float v1 = acc2[mt][nt][2*half + 1] + bb;
                        Vs[(r + half*8) * VS_STRIDE + col + 1] = v1;
                        part[mt][half] = fmaf(v1, v1, part[mt][half]);
                    }
                }
            }
        }
        // reduce across the 4 lanes sharing a row, then one atomic
#pragma unroll
        for (int mt = 0; mt < 2; mt++)
#pragma unroll
        for (int half = 0; half < 2; half++) {
            float s = part[mt][half];
            s += __shfl_xor_sync(0xFFFFFFFF, s, 1);
            s += __shfl_xor_sync(0xFFFFFFFF, s, 2);
            if ((lane & 3) == 0)
                atomicAdd(&trc[m0 + mt * 16 + (lane >> 2) + half * 8], s);
        }
    }
    __syncthreads();

    // ===================== stage 3: rho = L L^T / trace =====================
    {
        const float* Vs = reinterpret_cast<const float*>(smem + OFF_VS);
        const int row = tid & (ROWS - 1);
        const int ib  = tid >> 6;             // 0: even i, 1: odd i
        const float* vrow = &Vs[row * VS_STRIDE];
        const float invtr = 1.0f / trc[row];
        float* orow = &out[(size_t)(brow + row) * 256];
        if (ib == 0) {
            rho_row<0>(vrow, invtr, orow);  rho_row<2>(vrow, invtr, orow);
            rho_row<4>(vrow, invtr, orow);  rho_row<6>(vrow, invtr, orow);
            rho_row<8>(vrow, invtr, orow);  rho_row<10>(vrow, invtr, orow);
            rho_row<12>(vrow, invtr, orow); rho_row<14>(vrow, invtr, orow);
        } else {
            rho_row<1>(vrow, invtr, orow);  rho_row<3>(vrow, invtr, orow);
            rho_row<5>(vrow, invtr, orow);  rho_row<7>(vrow, invtr, orow);
            rho_row<9>(vrow, invtr, orow);  rho_row<11>(vrow, invtr, orow);
            rho_row<13>(vrow, invtr, orow); rho_row<15>(vrow, invtr, orow);
        }
    }
}

extern "C" void kernel_launch(void* const* d_in, const int* in_sizes, int n_in,
                              void* d_out, int out_size) {
    const float* x  = (const float*)d_in[0];
    const float* W1 = (const float*)d_in[1];
    const float* b1 = (const float*)d_in[2];
    const float* W2 = (const float*)d_in[3];
    const float* b2 = (const float*)d_in[4];
    float* out = (float*)d_out;

    const int batch  = in_sizes[0] / 256;   // 131072
    const int blocks = batch / ROWS;        // 2048

    prep_weights<<<200, 256>>>(W1, W2);

    cudaFuncSetAttribute(density_mlp_hmma,
                         cudaFuncAttributeMaxDynamicSharedMemorySize, SMEM_BYTES);
    density_mlp_hmma<<<blocks, THREADS, SMEM_BYTES>>>(x, b1, b2, out);
}